// round 14
// baseline (speedup 1.0000x reference)
#include <cuda_runtime.h>
#include <cuda_bf16.h>
#include <math.h>
#include <stdint.h>

#define Bn 2
#define Sn 2048
#define En 2048
#define Hn 16
#define NOPEn 64
#define ROPEn 32
#define Vn 64
#define KVRn 256
#define QKDn 96
#define BSn (Bn*Sn)
#define KD 288
#define KD2 144
#define SCALEF 0.10206207261596577f
#define NEGB (-1e30f)
#define LN1E4_D128 0.07195578415606394f
#define LN1E4_D16  0.5756462732485115f

/* ------------- scratch: PLANAR hl format (hi plane ++ lo plane, u32 bf16-pairs) ------ */
__device__ __align__(16) uint32_t g_hid[(size_t)2 * BSn * 1024];
__device__ __align__(16) uint32_t g_wq[(size_t)2 * 1536 * 1024];
__device__ __align__(16) uint32_t g_wkva[(size_t)2 * KD * 1024];
__device__ __align__(16) uint32_t g_wo[(size_t)2 * En * 512];
__device__ __align__(16) uint32_t g_wkvb[(size_t)2 * Hn * 128 * 128];
__device__ __align__(16) uint32_t g_q[(size_t)2 * BSn * 768];
__device__ __align__(16) float    g_kv[(size_t)BSn * KD];
__device__ __align__(16) uint32_t g_key[(size_t)2 * BSn * KD2];
__device__ __align__(16) uint32_t g_qp[(size_t)2 * Hn * BSn * KD2];
__device__ __align__(16) uint32_t g_wkT[(size_t)2 * Hn * KVRn * 32];
__device__ __align__(16) uint32_t g_vh[(size_t)2 * Hn * BSn * 32];
__device__ __align__(16) uint32_t g_v[(size_t)2 * BSn * 512];
__device__ __align__(16) uint32_t g_cbas[(size_t)2 * Sn * 128];
__device__ __align__(16) uint32_t g_pbas[(size_t)2 * Sn * 128];
__device__ __align__(16) uint32_t g_fcw[(size_t)2 * 64 * 128];
__device__ __align__(16) uint32_t g_fpw[(size_t)2 * 64 * 128];
__device__ __align__(16) float g_C2[Sn * 64];
__device__ __align__(16) float g_P2[Sn * 64];

#define HID_PL  ((long long)BSn*1024)
#define WQ_PL   ((long long)1536*1024)
#define WKVA_PL ((long long)KD*1024)
#define WO_PL   ((long long)En*512)
#define WKVB_PL ((long long)Hn*128*128)
#define Q_PL    ((long long)BSn*768)
#define KEY_PL  ((long long)BSn*KD2)
#define QP_PL   ((long long)Hn*BSn*KD2)
#define WKT_PL  ((long long)Hn*KVRn*32)
#define VH_PL   ((long long)Hn*BSn*32)
#define V_PL    ((long long)BSn*512)
#define BAS_PL  ((long long)Sn*128)
#define FW_PL   ((long long)64*128)

/* ==================== helpers ==================== */
__device__ __forceinline__ void mma16816(float* c, const uint32_t* a, const uint32_t* b) {
  asm volatile(
    "mma.sync.aligned.m16n8k16.row.col.f32.bf16.bf16.f32 "
    "{%0,%1,%2,%3}, {%4,%5,%6,%7}, {%8,%9}, {%0,%1,%2,%3};"
    : "+f"(c[0]), "+f"(c[1]), "+f"(c[2]), "+f"(c[3])
    : "r"(a[0]), "r"(a[1]), "r"(a[2]), "r"(a[3]), "r"(b[0]), "r"(b[1]));
}
#define LDM_X2T(r0_, r1_, addr) \
  asm volatile("ldmatrix.sync.aligned.m8n8.x2.trans.shared.b16 {%0,%1}, [%2];" \
               : "=r"(r0_), "=r"(r1_) : "r"(addr))
#define CP_ASYNC16(smaddr, gptr) \
  asm volatile("cp.async.cg.shared.global [%0], [%1], 16;" :: "r"(smaddr), "l"(gptr) : "memory")
#define CP_ASYNC16Z(smaddr, gptr, ssz) \
  asm volatile("cp.async.cg.shared.global [%0], [%1], 16, %2;" :: "r"(smaddr), "l"(gptr), "r"(ssz) : "memory")
#define CP_COMMIT() asm volatile("cp.async.commit_group;" ::: "memory")
#define CP_WAIT0()  asm volatile("cp.async.wait_group 0;" ::: "memory")
#define CP_WAIT1()  asm volatile("cp.async.wait_group 1;" ::: "memory")

__device__ __forceinline__ uint32_t smem_u32(const void* p) {
  uint32_t a;
  asm("{ .reg .u64 t; cvta.to.shared.u64 t, %1; cvt.u32.u64 %0, t; }" : "=r"(a) : "l"(p));
  return a;
}
__device__ __forceinline__ uint32_t pack_hi(float x, float y) {
  __nv_bfloat16 hx = __float2bfloat16_rn(x);
  __nv_bfloat16 hy = __float2bfloat16_rn(y);
  return ((uint32_t)__bfloat16_as_ushort(hy) << 16) | __bfloat16_as_ushort(hx);
}
__device__ __forceinline__ uint32_t pack_lo(float x, float y) {
  __nv_bfloat16 hx = __float2bfloat16_rn(x);
  __nv_bfloat16 hy = __float2bfloat16_rn(y);
  __nv_bfloat16 lx = __float2bfloat16_rn(x - __bfloat162float(hx));
  __nv_bfloat16 ly = __float2bfloat16_rn(y - __bfloat162float(hy));
  return ((uint32_t)__bfloat16_as_ushort(ly) << 16) | __bfloat16_as_ushort(lx);
}
__device__ __forceinline__ float2 unpk(uint32_t u) {
  return make_float2(__bfloat162float(__ushort_as_bfloat16((unsigned short)(u & 0xffff))),
                     __bfloat162float(__ushort_as_bfloat16((unsigned short)(u >> 16))));
}

/* ============ fp32 -> planar hl converter ============ */
__global__ void conv_hl(const float* __restrict__ in, uint32_t* __restrict__ outh,
                        long long plane, int npairs) {
  int i = blockIdx.x * 256 + threadIdx.x;
  if (i < npairs) {
    float2 v = ((const float2*)in)[i];
    outh[i] = pack_hi(v.x, v.y);
    outh[i + plane] = pack_lo(v.x, v.y);
  }
}

/* ============ positional-encoding bases (planar hl) ============ */
__global__ void gatebasis_kernel() {
  int s = blockIdx.x;
  int p = threadIdx.x;
  float dv = expf(-(float)p * LN1E4_D128);
  float aP = (float)s * dv;
  float aC = (float)(s >> 1) * dv;
  float sp = sinf(aP), cp = cosf(aP);
  float sc = sinf(aC), cc = cosf(aC);
  size_t ix = (size_t)s * 128 + p;
  g_pbas[ix] = pack_hi(sp, cp);  g_pbas[ix + BAS_PL] = pack_lo(sp, cp);
  g_cbas[ix] = pack_hi(sc, cc);  g_cbas[ix + BAS_PL] = pack_lo(sc, cc);
}

/* =============== batched tensor GEMM (planar hl): C = alpha*A[M,K]*B[N,K]^T ========== */
#define PITCH 20
#define PLSZ (128*PITCH)
#define STGu (4*PLSZ)
#define TGSM_BYTES (2*STGu*4)

__global__ __launch_bounds__(256, 2) void tgemmB(
    const uint32_t* __restrict__ A, long long aPl, int lda, long long sA,
    const uint32_t* __restrict__ B, long long bPl, int ldb, long long sB,
    float* __restrict__ C, uint32_t* __restrict__ Ch, long long cPl, int ldc, long long sC,
    int M, int N, int K, float alpha)
{
  A += (size_t)blockIdx.z * sA;
  B += (size_t)blockIdx.z * sB;
  if (C)  C  += (size_t)blockIdx.z * sC;
  if (Ch) Ch += (size_t)blockIdx.z * sC;
  extern __shared__ uint32_t dsm[];
  const uint32_t smB = smem_u32(dsm);

  const int tid = threadIdx.x;
  const int wid = tid >> 5, lane = tid & 31;
  const int g = lane >> 2, q = lane & 3;
  const int wm = (wid & 1) * 64;
  const int wn = (wid >> 1) * 32;
  const int bm = blockIdx.y * 128, bn = blockIdx.x * 128;

  const int lrow = tid >> 1, half = tid & 1;
  const uint32_t aZ = (bm + lrow < M) ? 16u : 0u;
  const uint32_t bZ = (bn + lrow < N) ? 16u : 0u;
  int arow = bm + lrow; if (arow >= M) arow = M - 1;
  int brow = bn + lrow; if (brow >= N) brow = N - 1;
  const uint32_t* ArH = A + (size_t)arow * lda + half * 8;
  const uint32_t* BrH = B + (size_t)brow * ldb + half * 8;
  const uint32_t woT = (uint32_t)(lrow * PITCH + half * 8);

  float acc[4][4][4];
#pragma unroll
  for (int i = 0; i < 4; i++)
#pragma unroll
    for (int j = 0; j < 4; j++)
#pragma unroll
      for (int t = 0; t < 4; t++) acc[i][j][t] = 0.f;

#define TG_ISSUE(kk, stg) do {                                             \
    uint32_t wo_ = smB + ((stg)*STGu + woT) * 4;                           \
    const uint32_t* pa_ = ArH + (kk) * 16;                                 \
    CP_ASYNC16Z(wo_,              pa_,       aZ);                          \
    CP_ASYNC16Z(wo_ + 16,         pa_ + 4,   aZ);                          \
    CP_ASYNC16Z(wo_ + PLSZ*4,     pa_ + aPl, aZ);                          \
    CP_ASYNC16Z(wo_ + PLSZ*4+16,  pa_ + aPl + 4, aZ);                      \
    const uint32_t* pb_ = BrH + (kk) * 16;                                 \
    CP_ASYNC16Z(wo_ + 2*PLSZ*4,    pb_,       bZ);                         \
    CP_ASYNC16Z(wo_ + 2*PLSZ*4+16, pb_ + 4,   bZ);                         \
    CP_ASYNC16Z(wo_ + 3*PLSZ*4,    pb_ + bPl, bZ);                         \
    CP_ASYNC16Z(wo_ + 3*PLSZ*4+16, pb_ + bPl + 4, bZ);                     \
  } while (0)

  const int nk = K >> 5;
  TG_ISSUE(0, 0);
  CP_COMMIT();

  for (int k = 0; k < nk; k++) {
    if (k + 1 < nk) {
      TG_ISSUE(k + 1, (k + 1) & 1);
      CP_COMMIT();
      CP_WAIT1();
    } else {
      CP_WAIT0();
    }
    __syncthreads();
    const uint32_t* smAh = dsm + (k & 1) * STGu;
    const uint32_t* smAl = smAh + PLSZ;
    const uint32_t* smBh = smAh + 2*PLSZ;
    const uint32_t* smBl = smAh + 3*PLSZ;
#pragma unroll
    for (int ks = 0; ks < 2; ks++) {
      uint32_t bh[4][2], bl[4][2];
#pragma unroll
      for (int nt = 0; nt < 4; nt++) {
        int r = (wn + nt * 8 + g) * PITCH + ks * 8 + q;
        bh[nt][0] = smBh[r]; bh[nt][1] = smBh[r + 4];
        bl[nt][0] = smBl[r]; bl[nt][1] = smBl[r + 4];
      }
#pragma unroll
      for (int mt = 0; mt < 4; mt++) {
        int r = (wm + mt * 16 + g) * PITCH + ks * 8 + q;
        uint32_t ah[4], al[4];
        ah[0] = smAh[r];     ah[1] = smAh[r + 8 * PITCH];
        ah[2] = smAh[r + 4]; ah[3] = smAh[r + 8 * PITCH + 4];
        al[0] = smAl[r];     al[1] = smAl[r + 8 * PITCH];
        al[2] = smAl[r + 4]; al[3] = smAl[r + 8 * PITCH + 4];
#pragma unroll
        for (int nt = 0; nt < 4; nt++) {
          mma16816(acc[mt][nt], ah, bh[nt]);
          mma16816(acc[mt][nt], ah, bl[nt]);
          mma16816(acc[mt][nt], al, bh[nt]);
        }
      }
    }
    __syncthreads();
  }

#pragma unroll
  for (int mt = 0; mt < 4; mt++) {
    int row = bm + wm + mt * 16 + g;
#pragma unroll
    for (int nt = 0; nt < 4; nt++) {
      int col = bn + wn + nt * 8 + q * 2;
      if (col >= N) continue;
      float a0 = alpha * acc[mt][nt][0], a1 = alpha * acc[mt][nt][1];
      float a2 = alpha * acc[mt][nt][2], a3 = alpha * acc[mt][nt][3];
      if (Ch) {
        if (row < M) {
          size_t ix = (size_t)row * ldc + (col >> 1);
          Ch[ix] = pack_hi(a0, a1); Ch[ix + cPl] = pack_lo(a0, a1);
        }
        if (row + 8 < M) {
          size_t ix = (size_t)(row + 8) * ldc + (col >> 1);
          Ch[ix] = pack_hi(a2, a3); Ch[ix + cPl] = pack_lo(a2, a3);
        }
      } else {
        if (row < M)     *(float2*)(C + (size_t)row * ldc + col)       = make_float2(a0, a1);
        if (row + 8 < M) *(float2*)(C + (size_t)(row + 8) * ldc + col) = make_float2(a2, a3);
      }
    }
  }
}

/* ============ layernorm + rope(k_pe) in place on g_kv ============ */
__global__ void ln_rope_kernel(const float* __restrict__ gam, const float* __restrict__ bet) {
  int row = blockIdx.x;
  float* kv = g_kv + (size_t)row * KD;
  int tid = threadIdx.x;
  float x = kv[tid];
  float s1 = x, s2 = x * x;
#pragma unroll
  for (int o = 16; o; o >>= 1) {
    s1 += __shfl_xor_sync(0xffffffffu, s1, o);
    s2 += __shfl_xor_sync(0xffffffffu, s2, o);
  }
  __shared__ float r1[8], r2[8], mv[2];
  int lane = tid & 31, wid = tid >> 5;
  if (lane == 0) { r1[wid] = s1; r2[wid] = s2; }
  __syncthreads();
  if (tid == 0) {
    float a = 0.f, c = 0.f;
#pragma unroll
    for (int i = 0; i < 8; i++) { a += r1[i]; c += r2[i]; }
    float mean = a * (1.f / 256.f);
    mv[0] = mean;
    mv[1] = rsqrtf(c * (1.f / 256.f) - mean * mean + 1e-5f);
  }
  __syncthreads();
  kv[tid] = (x - mv[0]) * mv[1] * gam[tid] + bet[tid];
  if (tid < 16) {
    int s = row & (Sn - 1);
    float freq = expf(-(float)tid * LN1E4_D16);
    float ang = (float)s * freq;
    float cs = cosf(ang), sn = sinf(ang);
    float x0 = kv[256 + 2*tid], x1 = kv[256 + 2*tid + 1];
    kv[256 + 2*tid]     = x0*cs - x1*sn;
    kv[256 + 2*tid + 1] = x0*sn + x1*cs;
  }
}

/* ============ sparse Wg gating -> planar hl keys (bias added here) ============ */
__global__ void gate_kernel(const float* __restrict__ cb, const float* __restrict__ pb) {
  int row = blockIdx.x;
  int s = row & (Sn - 1);
  int tid = threadIdx.x;
  __shared__ float d1[64], d2[64], w2s[2];
  if (tid < 64) {
    float c2 = g_C2[s*64 + tid] + cb[tid];
    d1[tid] = c2 * (g_P2[s*64 + tid] + pb[tid]);
    d2[tid] = (s & 1) ? c2 * (g_P2[(s-1)*64 + tid] + pb[tid]) : 0.f;
  }
  __syncthreads();
  if (tid == 0) {
    float a = 0.f, b = 0.f;
    for (int i = 0; i < 64; i++) { a += d1[i]; b += d2[i]; }
    w2s[0] = 1.f / (1.f + expf(-a));
    w2s[1] = 1.f / (1.f + expf(-b));
  }
  __syncthreads();
  float wtt = w2s[0], wpre = w2s[1];
  const float* kvr = g_kv + (size_t)row * KD;
  const float* kvp = kvr - KD;
  uint32_t* dsth = g_key + (size_t)row * KD2;
  bool odd = (s & 1);
  for (int c2 = tid; c2 < KD2; c2 += 128) {
    float v0 = wtt * kvr[2*c2],   v1 = wtt * kvr[2*c2+1];
    if (odd) { v0 += wpre * kvp[2*c2]; v1 += wpre * kvp[2*c2+1]; }
    dsth[c2] = pack_hi(v0, v1);
    dsth[c2 + KEY_PL] = pack_lo(v0, v1);
  }
}

/* ============ wkv_b first-64 rows transposed per head (planar) ============ */
__global__ void wkT_kernel(const float* __restrict__ wkvb) {
  int idx = blockIdx.x * 256 + threadIdx.x;
  int d2 = idx & 31;
  int c = (idx >> 5) & 255;
  int h = idx >> 13;
  float v0 = wkvb[((size_t)h * 128 + 2*d2) * 256 + c];
  float v1 = wkvb[((size_t)h * 128 + 2*d2 + 1) * 256 + c];
  size_t ix = ((size_t)h * 256 + c) * 32 + d2;
  g_wkT[ix] = pack_hi(v0, v1);
  g_wkT[ix + WKT_PL] = pack_lo(v0, v1);
}

/* ============ rope + scale q_pe (planar) ============ */
__global__ void qpack_kernel() {
  int row = blockIdx.x;
  int tid = threadIdx.x;
  int h = tid >> 4, i = tid & 15;
  int s = row & (Sn - 1);
  size_t qi = (size_t)row * 768 + h*48 + 32 + i;
  float2 hi = unpk(g_q[qi]), lo = unpk(g_q[qi + Q_PL]);
  float x0 = hi.x + lo.x, x1 = hi.y + lo.y;
  float freq = expf(-(float)i * LN1E4_D16);
  float ang = (float)s * freq;
  float cs = cosf(ang), sn = sinf(ang);
  float y0 = (x0*cs - x1*sn) * SCALEF;
  float y1 = (x0*sn + x1*cs) * SCALEF;
  size_t ox = ((size_t)h * BSn + row) * KD2 + 128 + i;
  g_qp[ox] = pack_hi(y0, y1);
  g_qp[ox + QP_PL] = pack_lo(y0, y1);
}

/* ============ attn: 32-query tiles, 2 CTAs/SM, V-absorbed flash ============ */
#define PQ 148
#define PVp 36
#define PP 20
#define QHo 0
#define QLo (32*PQ)                /* 4736 */
#define KHo (2*32*PQ)              /* 9472, lo plane at +32*PQ */
#define VHo (KHo + 2*32*PQ)        /* 18944; stage = 2*32*PVp = 2304 */
#define PFo (VHo + 2*2304)         /* 23552 */
#define PHo (PFo + 32*33)          /* 24608 */
#define PLo (PHo + 32*PP)          /* 25248 */
#define STo (PLo + 32*PP)          /* 25888 */
#define ATT_SMEM_U32 (STo + 128)
#define ATT_SMEM_BYTES (ATT_SMEM_U32 * 4)

__global__ __launch_bounds__(256, 2) void attn_mma() {
  extern __shared__ uint32_t sm4[];
  uint32_t* Qh = sm4 + QHo;
  uint32_t* Ql = sm4 + QLo;
  float*    Pf = (float*)(sm4 + PFo);
  uint32_t* Ph = sm4 + PHo;
  uint32_t* Pl = sm4 + PLo;
  float* mrow = (float*)(sm4 + STo);
  float* lrow = mrow + 32;
  float* sclv = lrow + 32;
  float* pdv  = sclv + 32;

  const int tid = threadIdx.x;
  const int lane = tid & 31, w = tid >> 5;
  const int g = lane >> 2, q = lane & 3;
  const int wm = (w & 1) * 16;     /* 2 row groups */
  const int wq4 = w >> 1;          /* 4 col groups */

  int idx = blockIdx.x;
  int qt = 63 - (idx & 63);
  int bh = idx >> 6;
  int h = bh & 15, b = bh >> 4;
  int s0 = qt * 32;
  int nit = (qt >> 1) + 1;

  const uint32_t* keyh = g_key + (size_t)b * Sn * KD2;
  const uint32_t* keyl = keyh + KEY_PL;
  const uint32_t* vhh  = g_vh + ((size_t)h * BSn + (size_t)b * Sn) * 32;
  const uint32_t* vhl  = vhh + VH_PL;
  const uint32_t smU = smem_u32(sm4);
  const int l16 = lane & 15;
  const int jr = tid >> 3, p8 = tid & 7;

  /* load Q tile 32x288 (planar) */
  {
    const uint32_t* qrh = g_qp + ((size_t)h * BSn + (size_t)b * Sn + s0 + jr) * KD2;
    const uint32_t* qrl = qrh + QP_PL;
#pragma unroll 18
    for (int w2 = p8; w2 < 144; w2 += 8) {
      Qh[jr*PQ + w2] = qrh[w2];
      Ql[jr*PQ + w2] = qrl[w2];
    }
  }
  if (tid < 32) { mrow[tid] = NEGB; lrow[tid] = 0.f; }

  float pacc[2][4];
#pragma unroll
  for (int nt = 0; nt < 2; nt++)
#pragma unroll
    for (int t = 0; t < 4; t++) pacc[nt][t] = 0.f;

  /* async: K single-buffer (32x144 u32/plane), V double-buffer (32x32/plane) */
#define ISSUE_KV(itn, stg) do {                                                     \
    size_t trow = (size_t)(2*(32*(itn) + jr) + 1);                                  \
    const uint32_t* gkh = keyh + trow * KD2;                                        \
    const uint32_t* gkl = keyl + trow * KD2;                                        \
    uint32_t kb = KHo + jr*PQ;                                                      \
    _Pragma("unroll")                                                               \
    for (int i_ = 0; i_ < 9; i_++) {                                                \
      int c_ = p8 + 8*i_;                                                           \
      int pl_ = (c_ >= 36);                                                         \
      int o_ = pl_ ? c_ - 36 : c_;                                                  \
      const uint32_t* g_ = (pl_ ? gkl : gkh) + o_*4;                                \
      CP_ASYNC16(smU + (kb + pl_*(32*PQ) + o_*4)*4, g_);                            \
    }                                                                               \
    const uint32_t* gvh = vhh + trow * 32;                                          \
    const uint32_t* gvl = vhl + trow * 32;                                          \
    uint32_t vb = VHo + (stg)*2304 + jr*PVp;                                        \
    _Pragma("unroll")                                                               \
    for (int i_ = 0; i_ < 2; i_++) {                                                \
      int c_ = p8 + 8*i_;                                                           \
      int pl_ = (c_ >= 8);                                                          \
      int o_ = c_ & 7;                                                              \
      const uint32_t* g_ = (pl_ ? gvl : gvh) + o_*4;                                \
      CP_ASYNC16(smU + (vb + pl_*1152 + o_*4)*4, g_);                               \
    }                                                                               \
  } while (0)

  ISSUE_KV(0, 0);
  CP_COMMIT();
  CP_WAIT0();
  __syncthreads();

  int st = 0;
  for (int it = 0; it < nit; it++) {
    bool lastt = (it == nit - 1);

    /* scores 32x32: warp tile 16 rows x 8 cols */
    float sacc[4];
#pragma unroll
    for (int t = 0; t < 4; t++) sacc[t] = 0.f;
#pragma unroll
    for (int ks = 0; ks < 18; ks++) {
      int ra = (wm + g) * PQ + ks * 8 + q;
      uint32_t ah[4], al[4];
      ah[0] = Qh[ra];     ah[1] = Qh[ra + 8*PQ];
      ah[2] = Qh[ra + 4]; ah[3] = Qh[ra + 8*PQ + 4];
      al[0] = Ql[ra];     al[1] = Ql[ra + 8*PQ];
      al[2] = Ql[ra + 4]; al[3] = Ql[ra + 8*PQ + 4];
      int rb = KHo + (wq4*8 + g) * PQ + ks * 8 + q;
      uint32_t bhf[2] = { sm4[rb], sm4[rb + 4] };
      uint32_t blf[2] = { sm4[rb + 32*PQ], sm4[rb + 32*PQ + 4] };
      mma16816(sacc, ah, bhf);
      mma16816(sacc, ah, blf);
      mma16816(sacc, al, bhf);
    }
    {
      int c = wq4*8 + 2*q;
      Pf[(wm+g)*33 + c]       = sacc[0];
      Pf[(wm+g)*33 + c + 1]   = sacc[1];
      Pf[(wm+g+8)*33 + c]     = sacc[2];
      Pf[(wm+g+8)*33 + c + 1] = sacc[3];
    }
    __syncthreads();   /* K consumed; Pf visible */

    if (!lastt) { ISSUE_KV(it + 1, st ^ 1); CP_COMMIT(); }

    /* online softmax: 8 threads per row, 4 cols each */
    {
      int r = tid >> 3, part = tid & 7;
      int jb = part * 4;
      float pv[4];
      float mx = NEGB;
#pragma unroll
      for (int i = 0; i < 4; i++) {
        float sc = Pf[r*33 + jb + i];
        if (lastt && (2*(32*it + jb + i) + 1 > s0 + r)) sc = NEGB;
        pv[i] = sc;
        mx = fmaxf(mx, sc);
      }
      mx = fmaxf(mx, __shfl_xor_sync(0xffffffffu, mx, 1));
      mx = fmaxf(mx, __shfl_xor_sync(0xffffffffu, mx, 2));
      mx = fmaxf(mx, __shfl_xor_sync(0xffffffffu, mx, 4));
      float mold = mrow[r];
      float mnew = fmaxf(mold, mx);
      float su = 0.f;
#pragma unroll
      for (int i = 0; i < 4; i++) {
        float p = __expf(pv[i] - mnew);
        pv[i] = p; su += p;
      }
      su += __shfl_xor_sync(0xffffffffu, su, 1);
      su += __shfl_xor_sync(0xffffffffu, su, 2);
      su += __shfl_xor_sync(0xffffffffu, su, 4);
      if (part == 0) {
        float s = __expf(mold - mnew);
        sclv[r] = s;
        lrow[r] = lrow[r] * s + su;
        mrow[r] = mnew;
      }
      Ph[r*PP + part*2]     = pack_hi(pv[0], pv[1]);
      Ph[r*PP + part*2 + 1] = pack_hi(pv[2], pv[3]);
      Pl[r*PP + part*2]     = pack_lo(pv[0], pv[1]);
      Pl[r*PP + part*2 + 1] = pack_lo(pv[2], pv[3]);
    }
    __syncthreads();

    /* rescale + PV: warp tile 16 rows x 16 V-cols */
    {
      float sl = sclv[wm + g], sh2 = sclv[wm + g + 8];
#pragma unroll
      for (int nt = 0; nt < 2; nt++) {
        pacc[nt][0] *= sl;  pacc[nt][1] *= sl;
        pacc[nt][2] *= sh2; pacc[nt][3] *= sh2;
      }
      uint32_t aph[2][4], apl[2][4];
#pragma unroll
      for (int ks = 0; ks < 2; ks++) {
        int rp = (wm + g) * PP + ks * 8 + q;
        aph[ks][0] = Ph[rp];     aph[ks][1] = Ph[rp + 8*PP];
        aph[ks][2] = Ph[rp + 4]; aph[ks][3] = Ph[rp + 8*PP + 4];
        apl[ks][0] = Pl[rp];     apl[ks][1] = Pl[rp + 8*PP];
        apl[ks][2] = Pl[rp + 4]; apl[ks][3] = Pl[rp + 8*PP + 4];
      }
      uint32_t vhB = smU + (uint32_t)(VHo + st*2304 + l16*PVp) * 4;
      uint32_t vlB = vhB + 1152u * 4;
#pragma unroll
      for (int nt = 0; nt < 2; nt++) {
        uint32_t co = (uint32_t)(wq4*8 + nt*4) * 4;
        uint32_t bh0[2], bl0[2], bh1[2], bl1[2];
        LDM_X2T(bh0[0], bh0[1], vhB + co);
        LDM_X2T(bh1[0], bh1[1], vhB + co + 16*PVp*4);
        LDM_X2T(bl0[0], bl0[1], vlB + co);
        LDM_X2T(bl1[0], bl1[1], vlB + co + 16*PVp*4);
        mma16816(pacc[nt], aph[0], bh0);
        mma16816(pacc[nt], aph[0], bl0);
        mma16816(pacc[nt], apl[0], bh0);
        mma16816(pacc[nt], aph[1], bh1);
        mma16816(pacc[nt], aph[1], bl1);
        mma16816(pacc[nt], apl[1], bh1);
      }
    }
    CP_WAIT0();
    __syncthreads();
    st ^= 1;
  }

  /* diagonal keys t = s0 + 2j (16 keys) -> reuse K and V stage 0 */
  {
    int j = tid >> 4, pp = tid & 15;
    size_t trow = (size_t)(s0 + 2*j);
    const uint32_t* krh = keyh + trow * KD2;
    const uint32_t* krl = keyl + trow * KD2;
#pragma unroll 9
    for (int i = 0; i < 9; i++) {
      int w2 = pp + 16*i;
      sm4[KHo + j*PQ + w2] = krh[w2];
      sm4[KHo + 32*PQ + j*PQ + w2] = krl[w2];
    }
    const uint32_t* gvh = vhh + trow * 32;
    const uint32_t* gvl = vhl + trow * 32;
#pragma unroll 2
    for (int i = 0; i < 2; i++) {
      int p = pp + 16*i;
      sm4[VHo + j*PVp + p] = gvh[p];
      sm4[VHo + 1152 + j*PVp + p] = gvl[p];
    }
  }
  __syncthreads();
  {
    int r = tid >> 3, part = tid & 7;
    float dot = 0.f;
    if (!(r & 1)) {
      int jj = r >> 1;
      for (int w2 = part*18; w2 < part*18 + 18; w2++) {
        float2 qh = unpk(Qh[r*PQ + w2]);
        float2 ql = unpk(Ql[r*PQ + w2]);
        float2 kh = unpk(sm4[KHo + jj*PQ + w2]);
        float2 kl = unpk(sm4[KHo + 32*PQ + jj*PQ + w2]);
        dot += qh.x*kh.x + qh.x*kl.x + ql.x*kh.x;
        dot += qh.y*kh.y + qh.y*kl.y + ql.y*kh.y;
      }
    }
    dot += __shfl_xor_sync(0xffffffffu, dot, 1);
    dot += __shfl_xor_sync(0xffffffffu, dot, 2);
    dot += __shfl_xor_sync(0xffffffffu, dot, 4);
    if (part == 0) {
      if (!(r & 1)) {
        float mold = mrow[r];
        float mnew = fmaxf(mold, dot);
        float s = __expf(mold - mnew);
        float pd = __expf(dot - mnew);
        sclv[r] = s; pdv[r] = pd;
        lrow[r] = lrow[r] * s + pd;
      } else {
        sclv[r] = 1.f; pdv[r] = 0.f;
      }
    }
  }
  __syncthreads();

  /* epilogue: (pacc*scl + pd*Vdiag)/l -> g_v planar [row][h*32 + p] */
  {
    uint32_t* vout = g_v + (size_t)(b * Sn + s0) * 512 + h * 32;
    int r0 = wm + g, r1 = wm + g + 8;
    float s0v = sclv[r0], s1v = sclv[r1];
    float p0v = pdv[r0],  p1v = pdv[r1];
    float il0 = 1.f / lrow[r0], il1 = 1.f / lrow[r1];
    bool ev = !(r0 & 1);
    int j0 = r0 >> 1, j1 = r1 >> 1;
#pragma unroll
    for (int nt = 0; nt < 2; nt++) {
      int p = wq4*8 + nt*4 + q;
      float kv00 = 0.f, kv01 = 0.f, kv10 = 0.f, kv11 = 0.f;
      if (ev) {
        float2 h0 = unpk(sm4[VHo + j0*PVp + p]);
        float2 l0 = unpk(sm4[VHo + 1152 + j0*PVp + p]);
        kv00 = h0.x + l0.x; kv01 = h0.y + l0.y;
        float2 h1 = unpk(sm4[VHo + j1*PVp + p]);
        float2 l1 = unpk(sm4[VHo + 1152 + j1*PVp + p]);
        kv10 = h1.x + l1.x; kv11 = h1.y + l1.y;
      }
      float f0 = (pacc[nt][0]*s0v + p0v*kv00)*il0;
      float f1 = (pacc[nt][1]*s0v + p0v*kv01)*il0;
      float f2 = (pacc[nt][2]*s1v + p1v*kv10)*il1;
      float f3 = (pacc[nt][3]*s1v + p1v*kv11)*il1;
      size_t i0 = (size_t)r0*512 + p, i1 = (size_t)r1*512 + p;
      vout[i0] = pack_hi(f0, f1); vout[i0 + V_PL] = pack_lo(f0, f1);
      vout[i1] = pack_hi(f2, f3); vout[i1 + V_PL] = pack_lo(f2, f3);
    }
  }
}

extern "C" void kernel_launch(void* const* d_in, const int* in_sizes, int n_in,
                              void* d_out, int out_size) {
  const float* hidden = (const float*)d_in[0];
  const float* wq     = (const float*)d_in[1];
  const float* wkv_a  = (const float*)d_in[2];
  const float* kvg    = (const float*)d_in[3];
  const float* kvb    = (const float*)d_in[4];
  const float* wkvb   = (const float*)d_in[5];
  const float* wo     = (const float*)d_in[6];
  const float* fcw    = (const float*)d_in[7];
  const float* fcb    = (const float*)d_in[8];
  const float* fpw    = (const float*)d_in[9];
  const float* fpb    = (const float*)d_in[10];
  float* out = (float*)d_out;

  uint32_t *pHid, *pWq, *pWkva, *pWo, *pWkvb, *pQ, *pKey, *pQp, *pWkT, *pVh, *pV;
  uint32_t *pCbas, *pPbas, *pFcw, *pFpw;
  float *pKv, *pC2, *pP2;
  cudaGetSymbolAddress((void**)&pHid,  g_hid);
  cudaGetSymbolAddress((void**)&pWq,   g_wq);
  cudaGetSymbolAddress((void**)&pWkva, g_wkva);
  cudaGetSymbolAddress((void**)&pWo,   g_wo);
  cudaGetSymbolAddress((void**)&pWkvb, g_wkvb);
  cudaGetSymbolAddress((void**)&pQ,    g_q);
  cudaGetSymbolAddress((void**)&pKv,   g_kv);
  cudaGetSymbolAddress((void**)&pKey,  g_key);
  cudaGetSymbolAddress((void**)&pQp,   g_qp);
  cudaGetSymbolAddress((void**)&pWkT,  g_wkT);
  cudaGetSymbolAddress((void**)&pVh,   g_vh);
  cudaGetSymbolAddress((void**)&pV,    g_v);
  cudaGetSymbolAddress((void**)&pCbas, g_cbas);
  cudaGetSymbolAddress((void**)&pPbas, g_pbas);
  cudaGetSymbolAddress((void**)&pFcw,  g_fcw);
  cudaGetSymbolAddress((void**)&pFpw,  g_fpw);
  cudaGetSymbolAddress((void**)&pC2,   g_C2);
  cudaGetSymbolAddress((void**)&pP2,   g_P2);

  cudaFuncSetAttribute(tgemmB, cudaFuncAttributeMaxDynamicSharedMemorySize, TGSM_BYTES);
  cudaFuncSetAttribute(attn_mma, cudaFuncAttributeMaxDynamicSharedMemorySize,
                       ATT_SMEM_BYTES);

  /* static streams/events: allocated once per process (R11 lesson) */
  static cudaStream_t s1 = nullptr, s2 = nullptr;
  static cudaEvent_t e0, eA, eWkT, eG, eVH, eJ1;
  if (s1 == nullptr) {
    cudaStreamCreateWithFlags(&s1, cudaStreamNonBlocking);
    cudaStreamCreateWithFlags(&s2, cudaStreamNonBlocking);
    cudaEventCreateWithFlags(&e0,   cudaEventDisableTiming);
    cudaEventCreateWithFlags(&eA,   cudaEventDisableTiming);
    cudaEventCreateWithFlags(&eWkT, cudaEventDisableTiming);
    cudaEventCreateWithFlags(&eG,   cudaEventDisableTiming);
    cudaEventCreateWithFlags(&eVH,  cudaEventDisableTiming);
    cudaEventCreateWithFlags(&eJ1,  cudaEventDisableTiming);
  }

  cudaEventRecord(e0, 0);

  /* main: hid + wkva converters */
  conv_hl<<<(BSn*1024 + 255)/256, 256>>>(hidden, pHid, HID_PL, BSn*1024);
  conv_hl<<<(KD*1024 + 255)/256, 256>>>(wkv_a, pWkva, WKVA_PL, KD*1024);
  cudaEventRecord(eA, 0);

  /* s1: gate bases + fc weights + C2/P2 GEMMs, then kv chain */
  cudaStreamWaitEvent(s1, e0, 0);
  gatebasis_kernel<<<Sn, 128, 0, s1>>>();
  conv_hl<<<(64*128 + 255)/256, 256, 0, s1>>>(fcw, pFcw, FW_PL, 64*128);
  conv_hl<<<(64*128 + 255)/256, 256, 0, s1>>>(fpw, pFpw, FW_PL, 64*128);
  tgemmB<<<dim3(1, 16, 1), 256, TGSM_BYTES, s1>>>(pCbas, BAS_PL, 128, 0,
                                   pFcw, FW_PL, 128, 0,
                                   pC2, nullptr, 0, 64, 0, Sn, 64, 256, 1.f);
  tgemmB<<<dim3(1, 16, 1), 256, TGSM_BYTES, s1>>>(pPbas, BAS_PL, 128, 0,
                                   pFpw, FW_PL, 128, 0,
                                   pP2, nullptr, 0, 64, 0, Sn, 64, 256, 1.f);
  cudaStreamWaitEvent(s1, eA, 0);
  tgemmB<<<dim3(3, 32, 1), 256, TGSM_BYTES, s1>>>(pHid, HID_PL, 1024, 0,
                                   pWkva, WKVA_PL, 1024, 0,
                                   pKv, nullptr, 0, KD, 0, 4096, KD, 2048, 1.f);
  ln_rope_kernel<<<BSn, 256, 0, s1>>>(kvg, kvb);
  gate_kernel<<<BSn, 128, 0, s1>>>(fcb, fpb);
  cudaEventRecord(eG, s1);

  /* s2: weight converters, then vh GEMM after gate */
  cudaStreamWaitEvent(s2, e0, 0);
  conv_hl<<<(Hn*128*128 + 255)/256, 256, 0, s2>>>(wkvb, pWkvb, WKVB_PL, Hn*128*128);
  wkT_kernel<<<(Hn*KVRn*32)/256, 256, 0, s2>>>(wkvb);
  cudaEventRecord(eWkT, s2);
  conv_hl<<<(En*512 + 255)/256, 256, 0, s2>>>(wo, pWo, WO_PL, En*512);
  cudaStreamWaitEvent(s2, eG, 0);
  tgemmB<<<dim3(1, 32, 16), 256, TGSM_BYTES, s2>>>(pKey, KEY_PL, 144, 0,
                                   pWkvb + 64*128, WKVB_PL, 128, (long long)128*128,
                                   nullptr, pVh, VH_PL, 32, (long long)BSn*32,
                                   4096, Vn, KVRn, 1.f);
  cudaEventRecord(eVH, s2);

  /* main: q-proj runs concurrently with s1/s2 */
  conv_hl<<<(1536*1024 + 255)/256, 256>>>(wq, pWq, WQ_PL, 1536*1024);
  tgemmB<<<dim3(12, 32, 1), 256, TGSM_BYTES>>>(pHid, HID_PL, 1024, 0, pWq, WQ_PL, 1024, 0,
                                   nullptr, pQ, Q_PL, 768, 0, 4096, 1536, 2048, 1.f);
  qpack_kernel<<<BSn, 256>>>();
  cudaStreamWaitEvent(0, eWkT, 0);
  tgemmB<<<dim3(2, 32, 16), 256, TGSM_BYTES>>>(pQ, Q_PL, 768, 48,
                                   pWkT, WKT_PL, 32, (long long)KVRn*32,
                                   nullptr, pQp, QP_PL, KD2, (long long)BSn*KD2,
                                   4096, KVRn, NOPEn, SCALEF);
  cudaStreamWaitEvent(0, eVH, 0);
  attn_mma<<<Bn*Hn*64, 256, ATT_SMEM_BYTES>>>();
  tgemmB<<<dim3(16, 32, 1), 256, TGSM_BYTES>>>(pV, V_PL, 512, 0, pWo, WO_PL, 512, 0,
                                   out, nullptr, 0, En, 0, 4096, En, Hn*Vn, 1.f);
  /* join s1/s2 back so capture terminates cleanly */
  cudaEventRecord(eJ1, 0);
  cudaStreamWaitEvent(s1, eJ1, 0);
  cudaStreamWaitEvent(s2, eJ1, 0);
}

// round 15
// speedup vs baseline: 1.0768x; 1.0768x over previous
#include <cuda_runtime.h>
#include <cuda_bf16.h>
#include <math.h>
#include <stdint.h>

#define Bn 2
#define Sn 2048
#define En 2048
#define Hn 16
#define NOPEn 64
#define ROPEn 32
#define Vn 64
#define KVRn 256
#define QKDn 96
#define BSn (Bn*Sn)
#define KD 288
#define KD2 144
#define SCALEF 0.10206207261596577f
#define NEGB (-1e30f)
#define LN1E4_D128 0.07195578415606394f
#define LN1E4_D16  0.5756462732485115f

/* ------------- scratch: PLANAR hl format (hi plane ++ lo plane, u32 bf16-pairs) ------ */
__device__ __align__(16) uint32_t g_hid[(size_t)2 * BSn * 1024];
__device__ __align__(16) uint32_t g_wq[(size_t)2 * 1536 * 1024];
__device__ __align__(16) uint32_t g_wkva[(size_t)2 * KD * 1024];
__device__ __align__(16) uint32_t g_wo[(size_t)2 * En * 512];
__device__ __align__(16) uint32_t g_wkvb[(size_t)2 * Hn * 128 * 128];
__device__ __align__(16) uint32_t g_q[(size_t)2 * BSn * 768];
__device__ __align__(16) float    g_kv[(size_t)BSn * KD];
__device__ __align__(16) uint32_t g_key[(size_t)2 * BSn * KD2];
__device__ __align__(16) uint32_t g_qp[(size_t)2 * Hn * BSn * KD2];
__device__ __align__(16) uint32_t g_wkT[(size_t)2 * Hn * KVRn * 32];
__device__ __align__(16) uint32_t g_vh[(size_t)2 * Hn * BSn * 32];
__device__ __align__(16) uint32_t g_v[(size_t)2 * BSn * 512];
__device__ __align__(16) uint32_t g_cbas[(size_t)2 * Sn * 128];
__device__ __align__(16) uint32_t g_pbas[(size_t)2 * Sn * 128];
__device__ __align__(16) uint32_t g_fcw[(size_t)2 * 64 * 128];
__device__ __align__(16) uint32_t g_fpw[(size_t)2 * 64 * 128];
__device__ __align__(16) float g_C2[Sn * 64];
__device__ __align__(16) float g_P2[Sn * 64];

#define HID_PL  ((long long)BSn*1024)
#define WQ_PL   ((long long)1536*1024)
#define WKVA_PL ((long long)KD*1024)
#define WO_PL   ((long long)En*512)
#define WKVB_PL ((long long)Hn*128*128)
#define Q_PL    ((long long)BSn*768)
#define KEY_PL  ((long long)BSn*KD2)
#define QP_PL   ((long long)Hn*BSn*KD2)
#define WKT_PL  ((long long)Hn*KVRn*32)
#define VH_PL   ((long long)Hn*BSn*32)
#define V_PL    ((long long)BSn*512)
#define BAS_PL  ((long long)Sn*128)
#define FW_PL   ((long long)64*128)

/* ==================== helpers ==================== */
__device__ __forceinline__ void mma16816(float* c, const uint32_t* a, const uint32_t* b) {
  asm volatile(
    "mma.sync.aligned.m16n8k16.row.col.f32.bf16.bf16.f32 "
    "{%0,%1,%2,%3}, {%4,%5,%6,%7}, {%8,%9}, {%0,%1,%2,%3};"
    : "+f"(c[0]), "+f"(c[1]), "+f"(c[2]), "+f"(c[3])
    : "r"(a[0]), "r"(a[1]), "r"(a[2]), "r"(a[3]), "r"(b[0]), "r"(b[1]));
}
#define LDM_X2T(r0_, r1_, addr) \
  asm volatile("ldmatrix.sync.aligned.m8n8.x2.trans.shared.b16 {%0,%1}, [%2];" \
               : "=r"(r0_), "=r"(r1_) : "r"(addr))
#define CP_ASYNC16(smaddr, gptr) \
  asm volatile("cp.async.cg.shared.global [%0], [%1], 16;" :: "r"(smaddr), "l"(gptr) : "memory")
#define CP_ASYNC16Z(smaddr, gptr, ssz) \
  asm volatile("cp.async.cg.shared.global [%0], [%1], 16, %2;" :: "r"(smaddr), "l"(gptr), "r"(ssz) : "memory")
#define CP_COMMIT() asm volatile("cp.async.commit_group;" ::: "memory")
#define CP_WAIT0()  asm volatile("cp.async.wait_group 0;" ::: "memory")
#define CP_WAIT1()  asm volatile("cp.async.wait_group 1;" ::: "memory")

__device__ __forceinline__ uint32_t smem_u32(const void* p) {
  uint32_t a;
  asm("{ .reg .u64 t; cvta.to.shared.u64 t, %1; cvt.u32.u64 %0, t; }" : "=r"(a) : "l"(p));
  return a;
}
__device__ __forceinline__ uint32_t pack_hi(float x, float y) {
  __nv_bfloat16 hx = __float2bfloat16_rn(x);
  __nv_bfloat16 hy = __float2bfloat16_rn(y);
  return ((uint32_t)__bfloat16_as_ushort(hy) << 16) | __bfloat16_as_ushort(hx);
}
__device__ __forceinline__ uint32_t pack_lo(float x, float y) {
  __nv_bfloat16 hx = __float2bfloat16_rn(x);
  __nv_bfloat16 hy = __float2bfloat16_rn(y);
  __nv_bfloat16 lx = __float2bfloat16_rn(x - __bfloat162float(hx));
  __nv_bfloat16 ly = __float2bfloat16_rn(y - __bfloat162float(hy));
  return ((uint32_t)__bfloat16_as_ushort(ly) << 16) | __bfloat16_as_ushort(lx);
}
__device__ __forceinline__ float2 unpk(uint32_t u) {
  return make_float2(__bfloat162float(__ushort_as_bfloat16((unsigned short)(u & 0xffff))),
                     __bfloat162float(__ushort_as_bfloat16((unsigned short)(u >> 16))));
}

/* ============ fp32 -> planar hl converter ============ */
__global__ void conv_hl(const float* __restrict__ in, uint32_t* __restrict__ outh,
                        long long plane, int npairs) {
  int i = blockIdx.x * 256 + threadIdx.x;
  if (i < npairs) {
    float2 v = ((const float2*)in)[i];
    outh[i] = pack_hi(v.x, v.y);
    outh[i + plane] = pack_lo(v.x, v.y);
  }
}

/* ============ positional-encoding bases (planar hl) ============ */
__global__ void gatebasis_kernel() {
  int s = blockIdx.x;
  int p = threadIdx.x;
  float dv = expf(-(float)p * LN1E4_D128);
  float aP = (float)s * dv;
  float aC = (float)(s >> 1) * dv;
  float sp = sinf(aP), cp = cosf(aP);
  float sc = sinf(aC), cc = cosf(aC);
  size_t ix = (size_t)s * 128 + p;
  g_pbas[ix] = pack_hi(sp, cp);  g_pbas[ix + BAS_PL] = pack_lo(sp, cp);
  g_cbas[ix] = pack_hi(sc, cc);  g_cbas[ix + BAS_PL] = pack_lo(sc, cc);
}

/* =============== batched tensor GEMM (planar hl): C = alpha*A[M,K]*B[N,K]^T ========== */
#define PITCH 20
#define PLSZ (128*PITCH)
#define STGu (4*PLSZ)
#define TGSM_BYTES (2*STGu*4)

__global__ __launch_bounds__(256, 2) void tgemmB(
    const uint32_t* __restrict__ A, long long aPl, int lda, long long sA,
    const uint32_t* __restrict__ B, long long bPl, int ldb, long long sB,
    float* __restrict__ C, uint32_t* __restrict__ Ch, long long cPl, int ldc, long long sC,
    int M, int N, int K, float alpha)
{
  A += (size_t)blockIdx.z * sA;
  B += (size_t)blockIdx.z * sB;
  if (C)  C  += (size_t)blockIdx.z * sC;
  if (Ch) Ch += (size_t)blockIdx.z * sC;
  extern __shared__ uint32_t dsm[];
  const uint32_t smB = smem_u32(dsm);

  const int tid = threadIdx.x;
  const int wid = tid >> 5, lane = tid & 31;
  const int g = lane >> 2, q = lane & 3;
  const int wm = (wid & 1) * 64;
  const int wn = (wid >> 1) * 32;
  const int bm = blockIdx.y * 128, bn = blockIdx.x * 128;

  const int lrow = tid >> 1, half = tid & 1;
  const uint32_t aZ = (bm + lrow < M) ? 16u : 0u;
  const uint32_t bZ = (bn + lrow < N) ? 16u : 0u;
  int arow = bm + lrow; if (arow >= M) arow = M - 1;
  int brow = bn + lrow; if (brow >= N) brow = N - 1;
  const uint32_t* ArH = A + (size_t)arow * lda + half * 8;
  const uint32_t* BrH = B + (size_t)brow * ldb + half * 8;
  const uint32_t woT = (uint32_t)(lrow * PITCH + half * 8);

  float acc[4][4][4];
#pragma unroll
  for (int i = 0; i < 4; i++)
#pragma unroll
    for (int j = 0; j < 4; j++)
#pragma unroll
      for (int t = 0; t < 4; t++) acc[i][j][t] = 0.f;

#define TG_ISSUE(kk, stg) do {                                             \
    uint32_t wo_ = smB + ((stg)*STGu + woT) * 4;                           \
    const uint32_t* pa_ = ArH + (kk) * 16;                                 \
    CP_ASYNC16Z(wo_,              pa_,       aZ);                          \
    CP_ASYNC16Z(wo_ + 16,         pa_ + 4,   aZ);                          \
    CP_ASYNC16Z(wo_ + PLSZ*4,     pa_ + aPl, aZ);                          \
    CP_ASYNC16Z(wo_ + PLSZ*4+16,  pa_ + aPl + 4, aZ);                      \
    const uint32_t* pb_ = BrH + (kk) * 16;                                 \
    CP_ASYNC16Z(wo_ + 2*PLSZ*4,    pb_,       bZ);                         \
    CP_ASYNC16Z(wo_ + 2*PLSZ*4+16, pb_ + 4,   bZ);                         \
    CP_ASYNC16Z(wo_ + 3*PLSZ*4,    pb_ + bPl, bZ);                         \
    CP_ASYNC16Z(wo_ + 3*PLSZ*4+16, pb_ + bPl + 4, bZ);                     \
  } while (0)

  const int nk = K >> 5;
  TG_ISSUE(0, 0);
  CP_COMMIT();

  for (int k = 0; k < nk; k++) {
    if (k + 1 < nk) {
      TG_ISSUE(k + 1, (k + 1) & 1);
      CP_COMMIT();
      CP_WAIT1();
    } else {
      CP_WAIT0();
    }
    __syncthreads();
    const uint32_t* smAh = dsm + (k & 1) * STGu;
    const uint32_t* smAl = smAh + PLSZ;
    const uint32_t* smBh = smAh + 2*PLSZ;
    const uint32_t* smBl = smAh + 3*PLSZ;
#pragma unroll
    for (int ks = 0; ks < 2; ks++) {
      uint32_t bh[4][2], bl[4][2];
#pragma unroll
      for (int nt = 0; nt < 4; nt++) {
        int r = (wn + nt * 8 + g) * PITCH + ks * 8 + q;
        bh[nt][0] = smBh[r]; bh[nt][1] = smBh[r + 4];
        bl[nt][0] = smBl[r]; bl[nt][1] = smBl[r + 4];
      }
#pragma unroll
      for (int mt = 0; mt < 4; mt++) {
        int r = (wm + mt * 16 + g) * PITCH + ks * 8 + q;
        uint32_t ah[4], al[4];
        ah[0] = smAh[r];     ah[1] = smAh[r + 8 * PITCH];
        ah[2] = smAh[r + 4]; ah[3] = smAh[r + 8 * PITCH + 4];
        al[0] = smAl[r];     al[1] = smAl[r + 8 * PITCH];
        al[2] = smAl[r + 4]; al[3] = smAl[r + 8 * PITCH + 4];
#pragma unroll
        for (int nt = 0; nt < 4; nt++) {
          mma16816(acc[mt][nt], ah, bh[nt]);
          mma16816(acc[mt][nt], ah, bl[nt]);
          mma16816(acc[mt][nt], al, bh[nt]);
        }
      }
    }
    __syncthreads();
  }

#pragma unroll
  for (int mt = 0; mt < 4; mt++) {
    int row = bm + wm + mt * 16 + g;
#pragma unroll
    for (int nt = 0; nt < 4; nt++) {
      int col = bn + wn + nt * 8 + q * 2;
      if (col >= N) continue;
      float a0 = alpha * acc[mt][nt][0], a1 = alpha * acc[mt][nt][1];
      float a2 = alpha * acc[mt][nt][2], a3 = alpha * acc[mt][nt][3];
      if (Ch) {
        if (row < M) {
          size_t ix = (size_t)row * ldc + (col >> 1);
          Ch[ix] = pack_hi(a0, a1); Ch[ix + cPl] = pack_lo(a0, a1);
        }
        if (row + 8 < M) {
          size_t ix = (size_t)(row + 8) * ldc + (col >> 1);
          Ch[ix] = pack_hi(a2, a3); Ch[ix + cPl] = pack_lo(a2, a3);
        }
      } else {
        if (row < M)     *(float2*)(C + (size_t)row * ldc + col)       = make_float2(a0, a1);
        if (row + 8 < M) *(float2*)(C + (size_t)(row + 8) * ldc + col) = make_float2(a2, a3);
      }
    }
  }
}

/* ============ layernorm + rope(k_pe) in place on g_kv ============ */
__global__ void ln_rope_kernel(const float* __restrict__ gam, const float* __restrict__ bet) {
  int row = blockIdx.x;
  float* kv = g_kv + (size_t)row * KD;
  int tid = threadIdx.x;
  float x = kv[tid];
  float s1 = x, s2 = x * x;
#pragma unroll
  for (int o = 16; o; o >>= 1) {
    s1 += __shfl_xor_sync(0xffffffffu, s1, o);
    s2 += __shfl_xor_sync(0xffffffffu, s2, o);
  }
  __shared__ float r1[8], r2[8], mv[2];
  int lane = tid & 31, wid = tid >> 5;
  if (lane == 0) { r1[wid] = s1; r2[wid] = s2; }
  __syncthreads();
  if (tid == 0) {
    float a = 0.f, c = 0.f;
#pragma unroll
    for (int i = 0; i < 8; i++) { a += r1[i]; c += r2[i]; }
    float mean = a * (1.f / 256.f);
    mv[0] = mean;
    mv[1] = rsqrtf(c * (1.f / 256.f) - mean * mean + 1e-5f);
  }
  __syncthreads();
  kv[tid] = (x - mv[0]) * mv[1] * gam[tid] + bet[tid];
  if (tid < 16) {
    int s = row & (Sn - 1);
    float freq = expf(-(float)tid * LN1E4_D16);
    float ang = (float)s * freq;
    float cs = cosf(ang), sn = sinf(ang);
    float x0 = kv[256 + 2*tid], x1 = kv[256 + 2*tid + 1];
    kv[256 + 2*tid]     = x0*cs - x1*sn;
    kv[256 + 2*tid + 1] = x0*sn + x1*cs;
  }
}

/* ============ sparse Wg gating -> planar hl keys (bias added here) ============ */
__global__ void gate_kernel(const float* __restrict__ cb, const float* __restrict__ pb) {
  int row = blockIdx.x;
  int s = row & (Sn - 1);
  int tid = threadIdx.x;
  __shared__ float d1[64], d2[64], w2s[2];
  if (tid < 64) {
    float c2 = g_C2[s*64 + tid] + cb[tid];
    d1[tid] = c2 * (g_P2[s*64 + tid] + pb[tid]);
    d2[tid] = (s & 1) ? c2 * (g_P2[(s-1)*64 + tid] + pb[tid]) : 0.f;
  }
  __syncthreads();
  if (tid == 0) {
    float a = 0.f, b = 0.f;
    for (int i = 0; i < 64; i++) { a += d1[i]; b += d2[i]; }
    w2s[0] = 1.f / (1.f + expf(-a));
    w2s[1] = 1.f / (1.f + expf(-b));
  }
  __syncthreads();
  float wtt = w2s[0], wpre = w2s[1];
  const float* kvr = g_kv + (size_t)row * KD;
  const float* kvp = kvr - KD;
  uint32_t* dsth = g_key + (size_t)row * KD2;
  bool odd = (s & 1);
  for (int c2 = tid; c2 < KD2; c2 += 128) {
    float v0 = wtt * kvr[2*c2],   v1 = wtt * kvr[2*c2+1];
    if (odd) { v0 += wpre * kvp[2*c2]; v1 += wpre * kvp[2*c2+1]; }
    dsth[c2] = pack_hi(v0, v1);
    dsth[c2 + KEY_PL] = pack_lo(v0, v1);
  }
}

/* ============ wkv_b first-64 rows transposed per head (planar) ============ */
__global__ void wkT_kernel(const float* __restrict__ wkvb) {
  int idx = blockIdx.x * 256 + threadIdx.x;
  int d2 = idx & 31;
  int c = (idx >> 5) & 255;
  int h = idx >> 13;
  float v0 = wkvb[((size_t)h * 128 + 2*d2) * 256 + c];
  float v1 = wkvb[((size_t)h * 128 + 2*d2 + 1) * 256 + c];
  size_t ix = ((size_t)h * 256 + c) * 32 + d2;
  g_wkT[ix] = pack_hi(v0, v1);
  g_wkT[ix + WKT_PL] = pack_lo(v0, v1);
}

/* ============ rope + scale q_pe (planar) ============ */
__global__ void qpack_kernel() {
  int row = blockIdx.x;
  int tid = threadIdx.x;
  int h = tid >> 4, i = tid & 15;
  int s = row & (Sn - 1);
  size_t qi = (size_t)row * 768 + h*48 + 32 + i;
  float2 hi = unpk(g_q[qi]), lo = unpk(g_q[qi + Q_PL]);
  float x0 = hi.x + lo.x, x1 = hi.y + lo.y;
  float freq = expf(-(float)i * LN1E4_D16);
  float ang = (float)s * freq;
  float cs = cosf(ang), sn = sinf(ang);
  float y0 = (x0*cs - x1*sn) * SCALEF;
  float y1 = (x0*sn + x1*cs) * SCALEF;
  size_t ox = ((size_t)h * BSn + row) * KD2 + 128 + i;
  g_qp[ox] = pack_hi(y0, y1);
  g_qp[ox + QP_PL] = pack_lo(y0, y1);
}

/* ============ attn: 64-query tiles, V-absorbed flash, cp.async K/V (R13 design) ===== */
#define PQ 148
#define PVp 36
#define PP 20
#define QHo 0
#define QLo (64*PQ)
#define KST0 (2*64*PQ)
#define VST0 (KST0 + 2*9472)
#define PFo  (VST0 + 2*2304)
#define PHo  (PFo + 64*33)
#define PLo  (PHo + 64*PP)
#define STo  (PLo + 64*PP)
#define ATT_SMEM_U32 (STo + 256)
#define ATT_SMEM_BYTES (ATT_SMEM_U32 * 4)

__global__ __launch_bounds__(256, 1) void attn_mma() {
  extern __shared__ uint32_t sm4[];
  uint32_t* Qh = sm4 + QHo;
  uint32_t* Ql = sm4 + QLo;
  float*    Pf = (float*)(sm4 + PFo);
  uint32_t* Ph = sm4 + PHo;
  uint32_t* Pl = sm4 + PLo;
  float* mrow = (float*)(sm4 + STo);
  float* lrow = mrow + 64;
  float* sclv = lrow + 64;
  float* pdv  = sclv + 64;

  const int tid = threadIdx.x;
  const int lane = tid & 31, w = tid >> 5;
  const int g = lane >> 2, q = lane & 3;
  const int wm = (w & 3) * 16;
  const int wn2 = w >> 2;

  int idx = blockIdx.x;
  int qt = 31 - (idx & 31);
  int bh = idx >> 5;
  int h = bh & 15, b = bh >> 4;
  int s0 = qt * 64;

  const uint32_t* keyh = g_key + (size_t)b * Sn * KD2;
  const uint32_t* keyl = keyh + KEY_PL;
  const uint32_t* vhh  = g_vh + ((size_t)h * BSn + (size_t)b * Sn) * 32;
  const uint32_t* vhl  = vhh + VH_PL;
  const uint32_t smU = smem_u32(sm4);
  const int l16 = lane & 15;
  const int jr = tid >> 3, p8 = tid & 7;

  {
    int r = tid >> 2, p0 = tid & 3;
    const uint32_t* qrh = g_qp + ((size_t)h * BSn + (size_t)b * Sn + s0 + r) * KD2;
    const uint32_t* qrl = qrh + QP_PL;
#pragma unroll 9
    for (int w2 = p0; w2 < 144; w2 += 4) {
      Qh[r*PQ + w2] = qrh[w2];
      Ql[r*PQ + w2] = qrl[w2];
    }
  }
  if (tid < 64) { mrow[tid] = NEGB; lrow[tid] = 0.f; }

  float pacc[4][4];
#pragma unroll
  for (int nt = 0; nt < 4; nt++)
#pragma unroll
    for (int t = 0; t < 4; t++) pacc[nt][t] = 0.f;

#define ISSUE_KV(itn, stg) do {                                                     \
    size_t trow = (size_t)(2*(32*(itn) + jr) + 1);                                  \
    const uint32_t* gkh = keyh + trow * KD2;                                        \
    const uint32_t* gkl = keyl + trow * KD2;                                        \
    uint32_t kb = KST0 + (stg)*9472 + jr*PQ;                                        \
    _Pragma("unroll")                                                               \
    for (int i_ = 0; i_ < 9; i_++) {                                                \
      int c_ = p8 + 8*i_;                                                           \
      int pl_ = (c_ >= 36);                                                         \
      int o_ = pl_ ? c_ - 36 : c_;                                                  \
      const uint32_t* g_ = (pl_ ? gkl : gkh) + o_*4;                                \
      CP_ASYNC16(smU + (kb + pl_*4736 + o_*4)*4, g_);                               \
    }                                                                               \
    const uint32_t* gvh = vhh + trow * 32;                                          \
    const uint32_t* gvl = vhl + trow * 32;                                          \
    uint32_t vb = VST0 + (stg)*2304 + jr*PVp;                                       \
    _Pragma("unroll")                                                               \
    for (int i_ = 0; i_ < 2; i_++) {                                                \
      int c_ = p8 + 8*i_;                                                           \
      int pl_ = (c_ >= 8);                                                          \
      int o_ = c_ & 7;                                                              \
      const uint32_t* g_ = (pl_ ? gvl : gvh) + o_*4;                                \
      CP_ASYNC16(smU + (vb + pl_*1152 + o_*4)*4, g_);                               \
    }                                                                               \
  } while (0)

  ISSUE_KV(0, 0);
  CP_COMMIT();
  CP_WAIT0();
  __syncthreads();

  int st = 0;
  for (int it = 0; it <= qt; it++) {
    bool lastt = (it == qt);
    if (!lastt) { ISSUE_KV(it + 1, st ^ 1); CP_COMMIT(); }

    const int kcur = KST0 + st*9472;
    float sacc[2][4];
#pragma unroll
    for (int nt = 0; nt < 2; nt++)
#pragma unroll
      for (int t = 0; t < 4; t++) sacc[nt][t] = 0.f;
#pragma unroll
    for (int ks = 0; ks < 18; ks++) {
      int ra = (wm + g) * PQ + ks * 8 + q;
      uint32_t ah[4], al[4];
      ah[0] = Qh[ra];     ah[1] = Qh[ra + 8*PQ];
      ah[2] = Qh[ra + 4]; ah[3] = Qh[ra + 8*PQ + 4];
      al[0] = Ql[ra];     al[1] = Ql[ra + 8*PQ];
      al[2] = Ql[ra + 4]; al[3] = Ql[ra + 8*PQ + 4];
#pragma unroll
      for (int nt = 0; nt < 2; nt++) {
        int rb = kcur + (wn2*16 + nt*8 + g) * PQ + ks * 8 + q;
        uint32_t bhf[2] = { sm4[rb], sm4[rb + 4] };
        uint32_t blf[2] = { sm4[rb + 4736], sm4[rb + 4736 + 4] };
        mma16816(sacc[nt], ah, bhf);
        mma16816(sacc[nt], ah, blf);
        mma16816(sacc[nt], al, bhf);
      }
    }
#pragma unroll
    for (int nt = 0; nt < 2; nt++) {
      int c = wn2*16 + nt*8 + 2*q;
      Pf[(wm+g)*33 + c]       = sacc[nt][0];
      Pf[(wm+g)*33 + c + 1]   = sacc[nt][1];
      Pf[(wm+g+8)*33 + c]     = sacc[nt][2];
      Pf[(wm+g+8)*33 + c + 1] = sacc[nt][3];
    }
    __syncthreads();

    {
      int r = tid >> 2, part = tid & 3;
      int jb = part * 8;
      float pv[8];
      float mx = NEGB;
#pragma unroll
      for (int i = 0; i < 8; i++) {
        float sc = Pf[r*33 + jb + i];
        if (lastt && (2*(32*it + jb + i) + 1 > s0 + r)) sc = NEGB;
        pv[i] = sc;
        mx = fmaxf(mx, sc);
      }
      mx = fmaxf(mx, __shfl_xor_sync(0xffffffffu, mx, 1));
      mx = fmaxf(mx, __shfl_xor_sync(0xffffffffu, mx, 2));
      float mold = mrow[r];
      float mnew = fmaxf(mold, mx);
      float su = 0.f;
#pragma unroll
      for (int i = 0; i < 8; i++) {
        float p = __expf(pv[i] - mnew);
        pv[i] = p; su += p;
      }
      su += __shfl_xor_sync(0xffffffffu, su, 1);
      su += __shfl_xor_sync(0xffffffffu, su, 2);
      if (part == 0) {
        float s = __expf(mold - mnew);
        sclv[r] = s;
        lrow[r] = lrow[r] * s + su;
        mrow[r] = mnew;
      }
#pragma unroll
      for (int ii = 0; ii < 4; ii++) {
        Ph[r*PP + part*4 + ii] = pack_hi(pv[2*ii], pv[2*ii+1]);
        Pl[r*PP + part*4 + ii] = pack_lo(pv[2*ii], pv[2*ii+1]);
      }
    }
    __syncthreads();

    {
      float sl = sclv[wm + g], sh2 = sclv[wm + g + 8];
#pragma unroll
      for (int nt = 0; nt < 4; nt++) {
        pacc[nt][0] *= sl;  pacc[nt][1] *= sl;
        pacc[nt][2] *= sh2; pacc[nt][3] *= sh2;
      }
      uint32_t aph[2][4], apl[2][4];
#pragma unroll
      for (int ks = 0; ks < 2; ks++) {
        int rp = (wm + g) * PP + ks * 8 + q;
        aph[ks][0] = Ph[rp];     aph[ks][1] = Ph[rp + 8*PP];
        aph[ks][2] = Ph[rp + 4]; aph[ks][3] = Ph[rp + 8*PP + 4];
        apl[ks][0] = Pl[rp];     apl[ks][1] = Pl[rp + 8*PP];
        apl[ks][2] = Pl[rp + 4]; apl[ks][3] = Pl[rp + 8*PP + 4];
      }
      uint32_t vhB = smU + (uint32_t)(VST0 + st*2304 + l16*PVp) * 4;
      uint32_t vlB = vhB + 1152u * 4;
#pragma unroll
      for (int nt = 0; nt < 4; nt++) {
        uint32_t co = (uint32_t)(wn2*16 + nt*4) * 4;
        uint32_t bh0[2], bl0[2], bh1[2], bl1[2];
        LDM_X2T(bh0[0], bh0[1], vhB + co);
        LDM_X2T(bh1[0], bh1[1], vhB + co + 16*PVp*4);
        LDM_X2T(bl0[0], bl0[1], vlB + co);
        LDM_X2T(bl1[0], bl1[1], vlB + co + 16*PVp*4);
        mma16816(pacc[nt], aph[0], bh0);
        mma16816(pacc[nt], aph[0], bl0);
        mma16816(pacc[nt], apl[0], bh0);
        mma16816(pacc[nt], aph[1], bh1);
        mma16816(pacc[nt], aph[1], bl1);
        mma16816(pacc[nt], apl[1], bh1);
      }
    }
    CP_WAIT0();
    __syncthreads();
    st ^= 1;
  }

  {
    size_t trow = (size_t)(s0 + 2*jr);
    const uint32_t* krh = keyh + trow * KD2;
    const uint32_t* krl = keyl + trow * KD2;
#pragma unroll 18
    for (int i = 0; i < 18; i++) {
      sm4[KST0 + jr*PQ + p8 + 8*i] = krh[p8 + 8*i];
      sm4[KST0 + 4736 + jr*PQ + p8 + 8*i] = krl[p8 + 8*i];
    }
    const uint32_t* gvh = vhh + trow * 32;
    const uint32_t* gvl = vhl + trow * 32;
#pragma unroll 4
    for (int i = 0; i < 4; i++) {
      sm4[VST0 + jr*PVp + (p8<<2) + i] = gvh[(p8<<2) + i];
      sm4[VST0 + 1152 + jr*PVp + (p8<<2) + i] = gvl[(p8<<2) + i];
    }
  }
  __syncthreads();
  {
    int r = tid >> 2, part = tid & 3;
    float dot = 0.f;
    if (!(r & 1)) {
      int jj = r >> 1;
      for (int w2 = part*36; w2 < part*36 + 36; w2++) {
        float2 qh = unpk(Qh[r*PQ + w2]);
        float2 ql = unpk(Ql[r*PQ + w2]);
        float2 kh = unpk(sm4[KST0 + jj*PQ + w2]);
        float2 kl = unpk(sm4[KST0 + 4736 + jj*PQ + w2]);
        dot += qh.x*kh.x + qh.x*kl.x + ql.x*kh.x;
        dot += qh.y*kh.y + qh.y*kl.y + ql.y*kh.y;
      }
    }
    dot += __shfl_xor_sync(0xffffffffu, dot, 1);
    dot += __shfl_xor_sync(0xffffffffu, dot, 2);
    if (part == 0) {
      if (!(r & 1)) {
        float mold = mrow[r];
        float mnew = fmaxf(mold, dot);
        float s = __expf(mold - mnew);
        float pd = __expf(dot - mnew);
        sclv[r] = s; pdv[r] = pd;
        lrow[r] = lrow[r] * s + pd;
      } else {
        sclv[r] = 1.f; pdv[r] = 0.f;
      }
    }
  }
  __syncthreads();

  {
    uint32_t* vout = g_v + (size_t)(b * Sn + s0) * 512 + h * 32;
    int r0 = wm + g, r1 = wm + g + 8;
    float s0v = sclv[r0], s1v = sclv[r1];
    float p0v = pdv[r0],  p1v = pdv[r1];
    float il0 = 1.f / lrow[r0], il1 = 1.f / lrow[r1];
    bool ev = !(r0 & 1);
    int j0 = r0 >> 1, j1 = r1 >> 1;
#pragma unroll
    for (int nt = 0; nt < 4; nt++) {
      int p = wn2*16 + nt*4 + q;
      float kv00 = 0.f, kv01 = 0.f, kv10 = 0.f, kv11 = 0.f;
      if (ev) {
        float2 h0 = unpk(sm4[VST0 + j0*PVp + p]);
        float2 l0 = unpk(sm4[VST0 + 1152 + j0*PVp + p]);
        kv00 = h0.x + l0.x; kv01 = h0.y + l0.y;
        float2 h1 = unpk(sm4[VST0 + j1*PVp + p]);
        float2 l1 = unpk(sm4[VST0 + 1152 + j1*PVp + p]);
        kv10 = h1.x + l1.x; kv11 = h1.y + l1.y;
      }
      float f0 = (pacc[nt][0]*s0v + p0v*kv00)*il0;
      float f1 = (pacc[nt][1]*s0v + p0v*kv01)*il0;
      float f2 = (pacc[nt][2]*s1v + p1v*kv10)*il1;
      float f3 = (pacc[nt][3]*s1v + p1v*kv11)*il1;
      size_t i0 = (size_t)r0*512 + p, i1 = (size_t)r1*512 + p;
      vout[i0] = pack_hi(f0, f1); vout[i0 + V_PL] = pack_lo(f0, f1);
      vout[i1] = pack_hi(f2, f3); vout[i1 + V_PL] = pack_lo(f2, f3);
    }
  }
}

extern "C" void kernel_launch(void* const* d_in, const int* in_sizes, int n_in,
                              void* d_out, int out_size) {
  const float* hidden = (const float*)d_in[0];
  const float* wq     = (const float*)d_in[1];
  const float* wkv_a  = (const float*)d_in[2];
  const float* kvg    = (const float*)d_in[3];
  const float* kvb    = (const float*)d_in[4];
  const float* wkvb   = (const float*)d_in[5];
  const float* wo     = (const float*)d_in[6];
  const float* fcw    = (const float*)d_in[7];
  const float* fcb    = (const float*)d_in[8];
  const float* fpw    = (const float*)d_in[9];
  const float* fpb    = (const float*)d_in[10];
  float* out = (float*)d_out;

  uint32_t *pHid, *pWq, *pWkva, *pWo, *pWkvb, *pQ, *pKey, *pQp, *pWkT, *pVh, *pV;
  uint32_t *pCbas, *pPbas, *pFcw, *pFpw;
  float *pKv, *pC2, *pP2;
  cudaGetSymbolAddress((void**)&pHid,  g_hid);
  cudaGetSymbolAddress((void**)&pWq,   g_wq);
  cudaGetSymbolAddress((void**)&pWkva, g_wkva);
  cudaGetSymbolAddress((void**)&pWo,   g_wo);
  cudaGetSymbolAddress((void**)&pWkvb, g_wkvb);
  cudaGetSymbolAddress((void**)&pQ,    g_q);
  cudaGetSymbolAddress((void**)&pKv,   g_kv);
  cudaGetSymbolAddress((void**)&pKey,  g_key);
  cudaGetSymbolAddress((void**)&pQp,   g_qp);
  cudaGetSymbolAddress((void**)&pWkT,  g_wkT);
  cudaGetSymbolAddress((void**)&pVh,   g_vh);
  cudaGetSymbolAddress((void**)&pV,    g_v);
  cudaGetSymbolAddress((void**)&pCbas, g_cbas);
  cudaGetSymbolAddress((void**)&pPbas, g_pbas);
  cudaGetSymbolAddress((void**)&pFcw,  g_fcw);
  cudaGetSymbolAddress((void**)&pFpw,  g_fpw);
  cudaGetSymbolAddress((void**)&pC2,   g_C2);
  cudaGetSymbolAddress((void**)&pP2,   g_P2);

  cudaFuncSetAttribute(tgemmB, cudaFuncAttributeMaxDynamicSharedMemorySize, TGSM_BYTES);
  cudaFuncSetAttribute(attn_mma, cudaFuncAttributeMaxDynamicSharedMemorySize,
                       ATT_SMEM_BYTES);

  /* static streams/events: allocated once per process */
  static cudaStream_t s1 = nullptr, s2 = nullptr;
  static cudaEvent_t e0, eA, eWq, eWkT, eG, eVH, eJ1;
  if (s1 == nullptr) {
    cudaStreamCreateWithFlags(&s1, cudaStreamNonBlocking);
    cudaStreamCreateWithFlags(&s2, cudaStreamNonBlocking);
    cudaEventCreateWithFlags(&e0,   cudaEventDisableTiming);
    cudaEventCreateWithFlags(&eA,   cudaEventDisableTiming);
    cudaEventCreateWithFlags(&eWq,  cudaEventDisableTiming);
    cudaEventCreateWithFlags(&eWkT, cudaEventDisableTiming);
    cudaEventCreateWithFlags(&eG,   cudaEventDisableTiming);
    cudaEventCreateWithFlags(&eVH,  cudaEventDisableTiming);
    cudaEventCreateWithFlags(&eJ1,  cudaEventDisableTiming);
  }

  cudaEventRecord(e0, 0);

  /* s2: wq converter first (overlaps hid conv on main), then wkvb/wkT/wo */
  cudaStreamWaitEvent(s2, e0, 0);
  conv_hl<<<(1536*1024 + 255)/256, 256, 0, s2>>>(wq, pWq, WQ_PL, 1536*1024);
  cudaEventRecord(eWq, s2);
  conv_hl<<<(Hn*128*128 + 255)/256, 256, 0, s2>>>(wkvb, pWkvb, WKVB_PL, Hn*128*128);
  wkT_kernel<<<(Hn*KVRn*32)/256, 256, 0, s2>>>(wkvb);
  cudaEventRecord(eWkT, s2);
  conv_hl<<<(En*512 + 255)/256, 256, 0, s2>>>(wo, pWo, WO_PL, En*512);

  /* s1: gate bases + fc weights + C2/P2 GEMMs, then kv chain */
  cudaStreamWaitEvent(s1, e0, 0);
  gatebasis_kernel<<<Sn, 128, 0, s1>>>();
  conv_hl<<<(64*128 + 255)/256, 256, 0, s1>>>(fcw, pFcw, FW_PL, 64*128);
  conv_hl<<<(64*128 + 255)/256, 256, 0, s1>>>(fpw, pFpw, FW_PL, 64*128);
  tgemmB<<<dim3(1, 16, 1), 256, TGSM_BYTES, s1>>>(pCbas, BAS_PL, 128, 0,
                                   pFcw, FW_PL, 128, 0,
                                   pC2, nullptr, 0, 64, 0, Sn, 64, 256, 1.f);
  tgemmB<<<dim3(1, 16, 1), 256, TGSM_BYTES, s1>>>(pPbas, BAS_PL, 128, 0,
                                   pFpw, FW_PL, 128, 0,
                                   pP2, nullptr, 0, 64, 0, Sn, 64, 256, 1.f);

  /* main: hid + wkva converters */
  conv_hl<<<(BSn*1024 + 255)/256, 256>>>(hidden, pHid, HID_PL, BSn*1024);
  conv_hl<<<(KD*1024 + 255)/256, 256>>>(wkv_a, pWkva, WKVA_PL, KD*1024);
  cudaEventRecord(eA, 0);

  /* s1 continues: kv-proj -> ln -> gate */
  cudaStreamWaitEvent(s1, eA, 0);
  tgemmB<<<dim3(3, 32, 1), 256, TGSM_BYTES, s1>>>(pHid, HID_PL, 1024, 0,
                                   pWkva, WKVA_PL, 1024, 0,
                                   pKv, nullptr, 0, KD, 0, 4096, KD, 2048, 1.f);
  ln_rope_kernel<<<BSn, 256, 0, s1>>>(kvg, kvb);
  gate_kernel<<<BSn, 128, 0, s1>>>(fcb, fpb);
  cudaEventRecord(eG, s1);

  /* s2: vh GEMM after gate */
  cudaStreamWaitEvent(s2, eG, 0);
  tgemmB<<<dim3(1, 32, 16), 256, TGSM_BYTES, s2>>>(pKey, KEY_PL, 144, 0,
                                   pWkvb + 64*128, WKVB_PL, 128, (long long)128*128,
                                   nullptr, pVh, VH_PL, 32, (long long)BSn*32,
                                   4096, Vn, KVRn, 1.f);
  cudaEventRecord(eVH, s2);

  /* main: q-proj (waits wq conv) runs concurrently with s1/s2 */
  cudaStreamWaitEvent(0, eWq, 0);
  tgemmB<<<dim3(12, 32, 1), 256, TGSM_BYTES>>>(pHid, HID_PL, 1024, 0, pWq, WQ_PL, 1024, 0,
                                   nullptr, pQ, Q_PL, 768, 0, 4096, 1536, 2048, 1.f);
  qpack_kernel<<<BSn, 256>>>();
  cudaStreamWaitEvent(0, eWkT, 0);
  tgemmB<<<dim3(2, 32, 16), 256, TGSM_BYTES>>>(pQ, Q_PL, 768, 48,
                                   pWkT, WKT_PL, 32, (long long)KVRn*32,
                                   nullptr, pQp, QP_PL, KD2, (long long)BSn*KD2,
                                   4096, KVRn, NOPEn, SCALEF);
  cudaStreamWaitEvent(0, eVH, 0);
  attn_mma<<<Bn*Hn*32, 256, ATT_SMEM_BYTES>>>();
  tgemmB<<<dim3(16, 32, 1), 256, TGSM_BYTES>>>(pV, V_PL, 512, 0, pWo, WO_PL, 512, 0,
                                   out, nullptr, 0, En, 0, 4096, En, Hn*Vn, 1.f);
  /* join s1/s2 back so capture terminates cleanly */
  cudaEventRecord(eJ1, 0);
  cudaStreamWaitEvent(s1, eJ1, 0);
  cudaStreamWaitEvent(s2, eJ1, 0);
}

// round 16
// speedup vs baseline: 1.0856x; 1.0081x over previous
#include <cuda_runtime.h>
#include <cuda_bf16.h>
#include <math.h>
#include <stdint.h>

#define Bn 2
#define Sn 2048
#define En 2048
#define Hn 16
#define NOPEn 64
#define ROPEn 32
#define Vn 64
#define KVRn 256
#define QKDn 96
#define BSn (Bn*Sn)
#define KD 288
#define KD2 144
#define SCALEF 0.10206207261596577f
#define NEGB (-1e30f)
#define LN1E4_D128 0.07195578415606394f
#define LN1E4_D16  0.5756462732485115f

/* ------------- scratch: PLANAR hl format (hi plane ++ lo plane, u32 bf16-pairs) ------ */
__device__ __align__(16) uint32_t g_hid[(size_t)2 * BSn * 1024];
__device__ __align__(16) uint32_t g_wq[(size_t)2 * 1536 * 1024];
__device__ __align__(16) uint32_t g_wkva[(size_t)2 * KD * 1024];
__device__ __align__(16) uint32_t g_wo[(size_t)2 * En * 512];
__device__ __align__(16) uint32_t g_wkvb[(size_t)2 * Hn * 128 * 128];
__device__ __align__(16) uint32_t g_q[(size_t)2 * BSn * 768];
__device__ __align__(16) float    g_kv[(size_t)BSn * KD];
__device__ __align__(16) uint32_t g_key[(size_t)2 * BSn * KD2];
__device__ __align__(16) uint32_t g_qp[(size_t)2 * Hn * BSn * KD2];
__device__ __align__(16) uint32_t g_wkT[(size_t)2 * Hn * KVRn * 32];
__device__ __align__(16) uint32_t g_vh[(size_t)2 * Hn * BSn * 32];
__device__ __align__(16) uint32_t g_v[(size_t)2 * BSn * 512];
__device__ __align__(16) uint32_t g_cbas[(size_t)2 * Sn * 128];
__device__ __align__(16) uint32_t g_pbas[(size_t)2 * Sn * 128];
__device__ __align__(16) uint32_t g_fcw[(size_t)2 * 64 * 128];
__device__ __align__(16) uint32_t g_fpw[(size_t)2 * 64 * 128];
__device__ __align__(16) float g_C2[Sn * 64];
__device__ __align__(16) float g_P2[Sn * 64];

#define HID_PL  ((long long)BSn*1024)
#define WQ_PL   ((long long)1536*1024)
#define WKVA_PL ((long long)KD*1024)
#define WO_PL   ((long long)En*512)
#define WKVB_PL ((long long)Hn*128*128)
#define Q_PL    ((long long)BSn*768)
#define KEY_PL  ((long long)BSn*KD2)
#define QP_PL   ((long long)Hn*BSn*KD2)
#define WKT_PL  ((long long)Hn*KVRn*32)
#define VH_PL   ((long long)Hn*BSn*32)
#define V_PL    ((long long)BSn*512)
#define BAS_PL  ((long long)Sn*128)
#define FW_PL   ((long long)64*128)

/* ==================== helpers ==================== */
__device__ __forceinline__ void mma16816(float* c, const uint32_t* a, const uint32_t* b) {
  asm volatile(
    "mma.sync.aligned.m16n8k16.row.col.f32.bf16.bf16.f32 "
    "{%0,%1,%2,%3}, {%4,%5,%6,%7}, {%8,%9}, {%0,%1,%2,%3};"
    : "+f"(c[0]), "+f"(c[1]), "+f"(c[2]), "+f"(c[3])
    : "r"(a[0]), "r"(a[1]), "r"(a[2]), "r"(a[3]), "r"(b[0]), "r"(b[1]));
}
#define LDM_X2T(r0_, r1_, addr) \
  asm volatile("ldmatrix.sync.aligned.m8n8.x2.trans.shared.b16 {%0,%1}, [%2];" \
               : "=r"(r0_), "=r"(r1_) : "r"(addr))
#define LDM_X4(r0_, r1_, r2_, r3_, addr) \
  asm volatile("ldmatrix.sync.aligned.m8n8.x4.shared.b16 {%0,%1,%2,%3}, [%4];" \
               : "=r"(r0_), "=r"(r1_), "=r"(r2_), "=r"(r3_) : "r"(addr))
#define LDM_X2(r0_, r1_, addr) \
  asm volatile("ldmatrix.sync.aligned.m8n8.x2.shared.b16 {%0,%1}, [%2];" \
               : "=r"(r0_), "=r"(r1_) : "r"(addr))
#define CP_ASYNC16(smaddr, gptr) \
  asm volatile("cp.async.cg.shared.global [%0], [%1], 16;" :: "r"(smaddr), "l"(gptr) : "memory")
#define CP_ASYNC16Z(smaddr, gptr, ssz) \
  asm volatile("cp.async.cg.shared.global [%0], [%1], 16, %2;" :: "r"(smaddr), "l"(gptr), "r"(ssz) : "memory")
#define CP_COMMIT() asm volatile("cp.async.commit_group;" ::: "memory")
#define CP_WAIT0()  asm volatile("cp.async.wait_group 0;" ::: "memory")
#define CP_WAIT1()  asm volatile("cp.async.wait_group 1;" ::: "memory")

__device__ __forceinline__ uint32_t smem_u32(const void* p) {
  uint32_t a;
  asm("{ .reg .u64 t; cvta.to.shared.u64 t, %1; cvt.u32.u64 %0, t; }" : "=r"(a) : "l"(p));
  return a;
}
__device__ __forceinline__ uint32_t pack_hi(float x, float y) {
  __nv_bfloat16 hx = __float2bfloat16_rn(x);
  __nv_bfloat16 hy = __float2bfloat16_rn(y);
  return ((uint32_t)__bfloat16_as_ushort(hy) << 16) | __bfloat16_as_ushort(hx);
}
__device__ __forceinline__ uint32_t pack_lo(float x, float y) {
  __nv_bfloat16 hx = __float2bfloat16_rn(x);
  __nv_bfloat16 hy = __float2bfloat16_rn(y);
  __nv_bfloat16 lx = __float2bfloat16_rn(x - __bfloat162float(hx));
  __nv_bfloat16 ly = __float2bfloat16_rn(y - __bfloat162float(hy));
  return ((uint32_t)__bfloat16_as_ushort(ly) << 16) | __bfloat16_as_ushort(lx);
}
__device__ __forceinline__ float2 unpk(uint32_t u) {
  return make_float2(__bfloat162float(__ushort_as_bfloat16((unsigned short)(u & 0xffff))),
                     __bfloat162float(__ushort_as_bfloat16((unsigned short)(u >> 16))));
}

/* ============ fp32 -> planar hl converter ============ */
__global__ void conv_hl(const float* __restrict__ in, uint32_t* __restrict__ outh,
                        long long plane, int npairs) {
  int i = blockIdx.x * 256 + threadIdx.x;
  if (i < npairs) {
    float2 v = ((const float2*)in)[i];
    outh[i] = pack_hi(v.x, v.y);
    outh[i + plane] = pack_lo(v.x, v.y);
  }
}

/* ============ positional-encoding bases (planar hl) ============ */
__global__ void gatebasis_kernel() {
  int s = blockIdx.x;
  int p = threadIdx.x;
  float dv = expf(-(float)p * LN1E4_D128);
  float aP = (float)s * dv;
  float aC = (float)(s >> 1) * dv;
  float sp = sinf(aP), cp = cosf(aP);
  float sc = sinf(aC), cc = cosf(aC);
  size_t ix = (size_t)s * 128 + p;
  g_pbas[ix] = pack_hi(sp, cp);  g_pbas[ix + BAS_PL] = pack_lo(sp, cp);
  g_cbas[ix] = pack_hi(sc, cc);  g_cbas[ix + BAS_PL] = pack_lo(sc, cc);
}

/* =============== batched tensor GEMM (planar hl): C = alpha*A[M,K]*B[N,K]^T ==========
   cp.async 2-stage double buffer, 2 CTAs/SM, ldmatrix fragment loads. */
#define PITCH 20
#define PLSZ (128*PITCH)
#define STGu (4*PLSZ)
#define TGSM_BYTES (2*STGu*4)

__global__ __launch_bounds__(256, 2) void tgemmB(
    const uint32_t* __restrict__ A, long long aPl, int lda, long long sA,
    const uint32_t* __restrict__ B, long long bPl, int ldb, long long sB,
    float* __restrict__ C, uint32_t* __restrict__ Ch, long long cPl, int ldc, long long sC,
    int M, int N, int K, float alpha)
{
  A += (size_t)blockIdx.z * sA;
  B += (size_t)blockIdx.z * sB;
  if (C)  C  += (size_t)blockIdx.z * sC;
  if (Ch) Ch += (size_t)blockIdx.z * sC;
  extern __shared__ uint32_t dsm[];
  const uint32_t smB = smem_u32(dsm);

  const int tid = threadIdx.x;
  const int wid = tid >> 5, lane = tid & 31;
  const int g = lane >> 2, q = lane & 3;
  const int wm = (wid & 1) * 64;
  const int wn = (wid >> 1) * 32;
  const int bm = blockIdx.y * 128, bn = blockIdx.x * 128;

  const int lt = lane >> 3, lr8 = lane & 7;
  const uint32_t aoffL = (uint32_t)(((wm + (lt & 1) * 8 + lr8) * PITCH + (lt >> 1) * 4) * 4);
  const uint32_t boffL = (uint32_t)(((wn + lr8) * PITCH + ((lane >> 3) & 1) * 4) * 4);

  const int lrow = tid >> 1, half = tid & 1;
  const uint32_t aZ = (bm + lrow < M) ? 16u : 0u;
  const uint32_t bZ = (bn + lrow < N) ? 16u : 0u;
  int arow = bm + lrow; if (arow >= M) arow = M - 1;
  int brow = bn + lrow; if (brow >= N) brow = N - 1;
  const uint32_t* ArH = A + (size_t)arow * lda + half * 8;
  const uint32_t* BrH = B + (size_t)brow * ldb + half * 8;
  const uint32_t woT = (uint32_t)(lrow * PITCH + half * 8);

  float acc[4][4][4];
#pragma unroll
  for (int i = 0; i < 4; i++)
#pragma unroll
    for (int j = 0; j < 4; j++)
#pragma unroll
      for (int t = 0; t < 4; t++) acc[i][j][t] = 0.f;

#define TG_ISSUE(kk, stg) do {                                             \
    uint32_t wo_ = smB + ((stg)*STGu + woT) * 4;                           \
    const uint32_t* pa_ = ArH + (kk) * 16;                                 \
    CP_ASYNC16Z(wo_,              pa_,       aZ);                          \
    CP_ASYNC16Z(wo_ + 16,         pa_ + 4,   aZ);                          \
    CP_ASYNC16Z(wo_ + PLSZ*4,     pa_ + aPl, aZ);                          \
    CP_ASYNC16Z(wo_ + PLSZ*4+16,  pa_ + aPl + 4, aZ);                      \
    const uint32_t* pb_ = BrH + (kk) * 16;                                 \
    CP_ASYNC16Z(wo_ + 2*PLSZ*4,    pb_,       bZ);                         \
    CP_ASYNC16Z(wo_ + 2*PLSZ*4+16, pb_ + 4,   bZ);                         \
    CP_ASYNC16Z(wo_ + 3*PLSZ*4,    pb_ + bPl, bZ);                         \
    CP_ASYNC16Z(wo_ + 3*PLSZ*4+16, pb_ + bPl + 4, bZ);                     \
  } while (0)

  const int nk = K >> 5;
  TG_ISSUE(0, 0);
  CP_COMMIT();

  for (int k = 0; k < nk; k++) {
    if (k + 1 < nk) {
      TG_ISSUE(k + 1, (k + 1) & 1);
      CP_COMMIT();
      CP_WAIT1();
    } else {
      CP_WAIT0();
    }
    __syncthreads();
    const uint32_t baseS = smB + ((k & 1) * STGu) * 4;
#pragma unroll
    for (int ks = 0; ks < 2; ks++) {
      const uint32_t kcol = baseS + ks * 32;
      uint32_t bh[4][2], bl[4][2];
#pragma unroll
      for (int nt = 0; nt < 4; nt++) {
        uint32_t ba = kcol + 2*PLSZ*4 + boffL + nt * (8*PITCH*4);
        LDM_X2(bh[nt][0], bh[nt][1], ba);
        LDM_X2(bl[nt][0], bl[nt][1], ba + PLSZ*4);
      }
#pragma unroll
      for (int mt = 0; mt < 4; mt++) {
        uint32_t aa = kcol + aoffL + mt * (16*PITCH*4);
        uint32_t ah[4], al[4];
        LDM_X4(ah[0], ah[1], ah[2], ah[3], aa);
        LDM_X4(al[0], al[1], al[2], al[3], aa + PLSZ*4);
#pragma unroll
        for (int nt = 0; nt < 4; nt++) {
          mma16816(acc[mt][nt], ah, bh[nt]);
          mma16816(acc[mt][nt], ah, bl[nt]);
          mma16816(acc[mt][nt], al, bh[nt]);
        }
      }
    }
    __syncthreads();
  }

#pragma unroll
  for (int mt = 0; mt < 4; mt++) {
    int row = bm + wm + mt * 16 + g;
#pragma unroll
    for (int nt = 0; nt < 4; nt++) {
      int col = bn + wn + nt * 8 + q * 2;
      if (col >= N) continue;
      float a0 = alpha * acc[mt][nt][0], a1 = alpha * acc[mt][nt][1];
      float a2 = alpha * acc[mt][nt][2], a3 = alpha * acc[mt][nt][3];
      if (Ch) {
        if (row < M) {
          size_t ix = (size_t)row * ldc + (col >> 1);
          Ch[ix] = pack_hi(a0, a1); Ch[ix + cPl] = pack_lo(a0, a1);
        }
        if (row + 8 < M) {
          size_t ix = (size_t)(row + 8) * ldc + (col >> 1);
          Ch[ix] = pack_hi(a2, a3); Ch[ix + cPl] = pack_lo(a2, a3);
        }
      } else {
        if (row < M)     *(float2*)(C + (size_t)row * ldc + col)       = make_float2(a0, a1);
        if (row + 8 < M) *(float2*)(C + (size_t)(row + 8) * ldc + col) = make_float2(a2, a3);
      }
    }
  }
}

/* ============ layernorm + rope(k_pe) in place on g_kv ============ */
__global__ void ln_rope_kernel(const float* __restrict__ gam, const float* __restrict__ bet) {
  int row = blockIdx.x;
  float* kv = g_kv + (size_t)row * KD;
  int tid = threadIdx.x;
  float x = kv[tid];
  float s1 = x, s2 = x * x;
#pragma unroll
  for (int o = 16; o; o >>= 1) {
    s1 += __shfl_xor_sync(0xffffffffu, s1, o);
    s2 += __shfl_xor_sync(0xffffffffu, s2, o);
  }
  __shared__ float r1[8], r2[8], mv[2];
  int lane = tid & 31, wid = tid >> 5;
  if (lane == 0) { r1[wid] = s1; r2[wid] = s2; }
  __syncthreads();
  if (tid == 0) {
    float a = 0.f, c = 0.f;
#pragma unroll
    for (int i = 0; i < 8; i++) { a += r1[i]; c += r2[i]; }
    float mean = a * (1.f / 256.f);
    mv[0] = mean;
    mv[1] = rsqrtf(c * (1.f / 256.f) - mean * mean + 1e-5f);
  }
  __syncthreads();
  kv[tid] = (x - mv[0]) * mv[1] * gam[tid] + bet[tid];
  if (tid < 16) {
    int s = row & (Sn - 1);
    float freq = expf(-(float)tid * LN1E4_D16);
    float ang = (float)s * freq;
    float cs = cosf(ang), sn = sinf(ang);
    float x0 = kv[256 + 2*tid], x1 = kv[256 + 2*tid + 1];
    kv[256 + 2*tid]     = x0*cs - x1*sn;
    kv[256 + 2*tid + 1] = x0*sn + x1*cs;
  }
}

/* ============ sparse Wg gating -> planar hl keys (bias added here) ============ */
__global__ void gate_kernel(const float* __restrict__ cb, const float* __restrict__ pb) {
  int row = blockIdx.x;
  int s = row & (Sn - 1);
  int tid = threadIdx.x;
  __shared__ float d1[64], d2[64], w2s[2];
  if (tid < 64) {
    float c2 = g_C2[s*64 + tid] + cb[tid];
    d1[tid] = c2 * (g_P2[s*64 + tid] + pb[tid]);
    d2[tid] = (s & 1) ? c2 * (g_P2[(s-1)*64 + tid] + pb[tid]) : 0.f;
  }
  __syncthreads();
  if (tid == 0) {
    float a = 0.f, b = 0.f;
    for (int i = 0; i < 64; i++) { a += d1[i]; b += d2[i]; }
    w2s[0] = 1.f / (1.f + expf(-a));
    w2s[1] = 1.f / (1.f + expf(-b));
  }
  __syncthreads();
  float wtt = w2s[0], wpre = w2s[1];
  const float* kvr = g_kv + (size_t)row * KD;
  const float* kvp = kvr - KD;
  uint32_t* dsth = g_key + (size_t)row * KD2;
  bool odd = (s & 1);
  for (int c2 = tid; c2 < KD2; c2 += 128) {
    float v0 = wtt * kvr[2*c2],   v1 = wtt * kvr[2*c2+1];
    if (odd) { v0 += wpre * kvp[2*c2]; v1 += wpre * kvp[2*c2+1]; }
    dsth[c2] = pack_hi(v0, v1);
    dsth[c2 + KEY_PL] = pack_lo(v0, v1);
  }
}

/* ============ wkv_b first-64 rows transposed per head (planar) ============ */
__global__ void wkT_kernel(const float* __restrict__ wkvb) {
  int idx = blockIdx.x * 256 + threadIdx.x;
  int d2 = idx & 31;
  int c = (idx >> 5) & 255;
  int h = idx >> 13;
  float v0 = wkvb[((size_t)h * 128 + 2*d2) * 256 + c];
  float v1 = wkvb[((size_t)h * 128 + 2*d2 + 1) * 256 + c];
  size_t ix = ((size_t)h * 256 + c) * 32 + d2;
  g_wkT[ix] = pack_hi(v0, v1);
  g_wkT[ix + WKT_PL] = pack_lo(v0, v1);
}

/* ============ rope + scale q_pe (planar) ============ */
__global__ void qpack_kernel() {
  int row = blockIdx.x;
  int tid = threadIdx.x;
  int h = tid >> 4, i = tid & 15;
  int s = row & (Sn - 1);
  size_t qi = (size_t)row * 768 + h*48 + 32 + i;
  float2 hi = unpk(g_q[qi]), lo = unpk(g_q[qi + Q_PL]);
  float x0 = hi.x + lo.x, x1 = hi.y + lo.y;
  float freq = expf(-(float)i * LN1E4_D16);
  float ang = (float)s * freq;
  float cs = cosf(ang), sn = sinf(ang);
  float y0 = (x0*cs - x1*sn) * SCALEF;
  float y1 = (x0*sn + x1*cs) * SCALEF;
  size_t ox = ((size_t)h * BSn + row) * KD2 + 128 + i;
  g_qp[ox] = pack_hi(y0, y1);
  g_qp[ox + QP_PL] = pack_lo(y0, y1);
}

/* ============ attn: 64-query tiles, V-absorbed flash, ldmatrix fragments ============ */
#define PQ 148
#define PVp 36
#define PP 20
#define QHo 0
#define QLo (64*PQ)
#define KST0 (2*64*PQ)
#define VST0 (KST0 + 2*9472)
#define PFo  (VST0 + 2*2304)
#define PHo  (PFo + 64*33)
#define PLo  (PHo + 64*PP)
#define STo  (PLo + 64*PP)
#define ATT_SMEM_U32 (STo + 256)
#define ATT_SMEM_BYTES (ATT_SMEM_U32 * 4)

__global__ __launch_bounds__(256, 1) void attn_mma() {
  extern __shared__ uint32_t sm4[];
  uint32_t* Qh = sm4 + QHo;
  uint32_t* Ql = sm4 + QLo;
  float*    Pf = (float*)(sm4 + PFo);
  uint32_t* Ph = sm4 + PHo;
  uint32_t* Pl = sm4 + PLo;
  float* mrow = (float*)(sm4 + STo);
  float* lrow = mrow + 64;
  float* sclv = lrow + 64;
  float* pdv  = sclv + 64;

  const int tid = threadIdx.x;
  const int lane = tid & 31, w = tid >> 5;
  const int g = lane >> 2, q = lane & 3;
  const int wm = (w & 3) * 16;
  const int wn2 = w >> 2;

  int idx = blockIdx.x;
  int qt = 31 - (idx & 31);
  int bh = idx >> 5;
  int h = bh & 15, b = bh >> 4;
  int s0 = qt * 64;

  const uint32_t* keyh = g_key + (size_t)b * Sn * KD2;
  const uint32_t* keyl = keyh + KEY_PL;
  const uint32_t* vhh  = g_vh + ((size_t)h * BSn + (size_t)b * Sn) * 32;
  const uint32_t* vhl  = vhh + VH_PL;
  const uint32_t smU = smem_u32(sm4);
  const int l16 = lane & 15;
  const int jr = tid >> 3, p8 = tid & 7;

  const int lt = lane >> 3, lr8 = lane & 7;
  const uint32_t aoffQ = (uint32_t)(((wm + (lt & 1) * 8 + lr8) * PQ + (lt >> 1) * 4) * 4);
  const uint32_t boffK = (uint32_t)(((wn2*16 + lr8) * PQ + ((lane >> 3) & 1) * 4) * 4);
  const uint32_t aoffP = (uint32_t)(((wm + (lt & 1) * 8 + lr8) * PP + (lt >> 1) * 4) * 4);

  {
    int r = tid >> 2, p0 = tid & 3;
    const uint32_t* qrh = g_qp + ((size_t)h * BSn + (size_t)b * Sn + s0 + r) * KD2;
    const uint32_t* qrl = qrh + QP_PL;
#pragma unroll 9
    for (int w2 = p0; w2 < 144; w2 += 4) {
      Qh[r*PQ + w2] = qrh[w2];
      Ql[r*PQ + w2] = qrl[w2];
    }
  }
  if (tid < 64) { mrow[tid] = NEGB; lrow[tid] = 0.f; }

  float pacc[4][4];
#pragma unroll
  for (int nt = 0; nt < 4; nt++)
#pragma unroll
    for (int t = 0; t < 4; t++) pacc[nt][t] = 0.f;

#define ISSUE_KV(itn, stg) do {                                                     \
    size_t trow = (size_t)(2*(32*(itn) + jr) + 1);                                  \
    const uint32_t* gkh = keyh + trow * KD2;                                        \
    const uint32_t* gkl = keyl + trow * KD2;                                        \
    uint32_t kb = KST0 + (stg)*9472 + jr*PQ;                                        \
    _Pragma("unroll")                                                               \
    for (int i_ = 0; i_ < 9; i_++) {                                                \
      int c_ = p8 + 8*i_;                                                           \
      int pl_ = (c_ >= 36);                                                         \
      int o_ = pl_ ? c_ - 36 : c_;                                                  \
      const uint32_t* g_ = (pl_ ? gkl : gkh) + o_*4;                                \
      CP_ASYNC16(smU + (kb + pl_*4736 + o_*4)*4, g_);                               \
    }                                                                               \
    const uint32_t* gvh = vhh + trow * 32;                                          \
    const uint32_t* gvl = vhl + trow * 32;                                          \
    uint32_t vb = VST0 + (stg)*2304 + jr*PVp;                                       \
    _Pragma("unroll")                                                               \
    for (int i_ = 0; i_ < 2; i_++) {                                                \
      int c_ = p8 + 8*i_;                                                           \
      int pl_ = (c_ >= 8);                                                          \
      int o_ = c_ & 7;                                                              \
      const uint32_t* g_ = (pl_ ? gvl : gvh) + o_*4;                                \
      CP_ASYNC16(smU + (vb + pl_*1152 + o_*4)*4, g_);                               \
    }                                                                               \
  } while (0)

  ISSUE_KV(0, 0);
  CP_COMMIT();
  CP_WAIT0();
  __syncthreads();

  int st = 0;
  for (int it = 0; it <= qt; it++) {
    bool lastt = (it == qt);
    if (!lastt) { ISSUE_KV(it + 1, st ^ 1); CP_COMMIT(); }

    const uint32_t kbase = smU + (uint32_t)(KST0 + st*9472) * 4;
    float sacc[2][4];
#pragma unroll
    for (int nt = 0; nt < 2; nt++)
#pragma unroll
      for (int t = 0; t < 4; t++) sacc[nt][t] = 0.f;
#pragma unroll
    for (int ks = 0; ks < 18; ks++) {
      uint32_t aa = smU + aoffQ + ks * 32;
      uint32_t ah[4], al[4];
      LDM_X4(ah[0], ah[1], ah[2], ah[3], aa);
      LDM_X4(al[0], al[1], al[2], al[3], aa + QLo*4);
#pragma unroll
      for (int nt = 0; nt < 2; nt++) {
        uint32_t ba = kbase + boffK + nt * (8*PQ*4) + ks * 32;
        uint32_t bhf[2], blf[2];
        LDM_X2(bhf[0], bhf[1], ba);
        LDM_X2(blf[0], blf[1], ba + 4736*4);
        mma16816(sacc[nt], ah, bhf);
        mma16816(sacc[nt], ah, blf);
        mma16816(sacc[nt], al, bhf);
      }
    }
#pragma unroll
    for (int nt = 0; nt < 2; nt++) {
      int c = wn2*16 + nt*8 + 2*q;
      Pf[(wm+g)*33 + c]       = sacc[nt][0];
      Pf[(wm+g)*33 + c + 1]   = sacc[nt][1];
      Pf[(wm+g+8)*33 + c]     = sacc[nt][2];
      Pf[(wm+g+8)*33 + c + 1] = sacc[nt][3];
    }
    __syncthreads();

    {
      int r = tid >> 2, part = tid & 3;
      int jb = part * 8;
      float pv[8];
      float mx = NEGB;
#pragma unroll
      for (int i = 0; i < 8; i++) {
        float sc = Pf[r*33 + jb + i];
        if (lastt && (2*(32*it + jb + i) + 1 > s0 + r)) sc = NEGB;
        pv[i] = sc;
        mx = fmaxf(mx, sc);
      }
      mx = fmaxf(mx, __shfl_xor_sync(0xffffffffu, mx, 1));
      mx = fmaxf(mx, __shfl_xor_sync(0xffffffffu, mx, 2));
      float mold = mrow[r];
      float mnew = fmaxf(mold, mx);
      float su = 0.f;
#pragma unroll
      for (int i = 0; i < 8; i++) {
        float p = __expf(pv[i] - mnew);
        pv[i] = p; su += p;
      }
      su += __shfl_xor_sync(0xffffffffu, su, 1);
      su += __shfl_xor_sync(0xffffffffu, su, 2);
      if (part == 0) {
        float s = __expf(mold - mnew);
        sclv[r] = s;
        lrow[r] = lrow[r] * s + su;
        mrow[r] = mnew;
      }
#pragma unroll
      for (int ii = 0; ii < 4; ii++) {
        Ph[r*PP + part*4 + ii] = pack_hi(pv[2*ii], pv[2*ii+1]);
        Pl[r*PP + part*4 + ii] = pack_lo(pv[2*ii], pv[2*ii+1]);
      }
    }
    __syncthreads();

    {
      float sl = sclv[wm + g], sh2 = sclv[wm + g + 8];
#pragma unroll
      for (int nt = 0; nt < 4; nt++) {
        pacc[nt][0] *= sl;  pacc[nt][1] *= sl;
        pacc[nt][2] *= sh2; pacc[nt][3] *= sh2;
      }
      uint32_t aph[2][4], apl[2][4];
#pragma unroll
      for (int ks = 0; ks < 2; ks++) {
        uint32_t pa = smU + PHo*4 + aoffP + ks * 32;
        LDM_X4(aph[ks][0], aph[ks][1], aph[ks][2], aph[ks][3], pa);
        LDM_X4(apl[ks][0], apl[ks][1], apl[ks][2], apl[ks][3], pa + (PLo - PHo)*4);
      }
      uint32_t vhB = smU + (uint32_t)(VST0 + st*2304 + l16*PVp) * 4;
      uint32_t vlB = vhB + 1152u * 4;
#pragma unroll
      for (int nt = 0; nt < 4; nt++) {
        uint32_t co = (uint32_t)(wn2*16 + nt*4) * 4;
        uint32_t bh0[2], bl0[2], bh1[2], bl1[2];
        LDM_X2T(bh0[0], bh0[1], vhB + co);
        LDM_X2T(bh1[0], bh1[1], vhB + co + 16*PVp*4);
        LDM_X2T(bl0[0], bl0[1], vlB + co);
        LDM_X2T(bl1[0], bl1[1], vlB + co + 16*PVp*4);
        mma16816(pacc[nt], aph[0], bh0);
        mma16816(pacc[nt], aph[0], bl0);
        mma16816(pacc[nt], apl[0], bh0);
        mma16816(pacc[nt], aph[1], bh1);
        mma16816(pacc[nt], aph[1], bl1);
        mma16816(pacc[nt], apl[1], bh1);
      }
    }
    CP_WAIT0();
    __syncthreads();
    st ^= 1;
  }

  {
    size_t trow = (size_t)(s0 + 2*jr);
    const uint32_t* krh = keyh + trow * KD2;
    const uint32_t* krl = keyl + trow * KD2;
#pragma unroll 18
    for (int i = 0; i < 18; i++) {
      sm4[KST0 + jr*PQ + p8 + 8*i] = krh[p8 + 8*i];
      sm4[KST0 + 4736 + jr*PQ + p8 + 8*i] = krl[p8 + 8*i];
    }
    const uint32_t* gvh = vhh + trow * 32;
    const uint32_t* gvl = vhl + trow * 32;
#pragma unroll 4
    for (int i = 0; i < 4; i++) {
      sm4[VST0 + jr*PVp + (p8<<2) + i] = gvh[(p8<<2) + i];
      sm4[VST0 + 1152 + jr*PVp + (p8<<2) + i] = gvl[(p8<<2) + i];
    }
  }
  __syncthreads();
  {
    int r = tid >> 2, part = tid & 3;
    float dot = 0.f;
    if (!(r & 1)) {
      int jj = r >> 1;
      for (int w2 = part*36; w2 < part*36 + 36; w2++) {
        float2 qh = unpk(Qh[r*PQ + w2]);
        float2 ql = unpk(Ql[r*PQ + w2]);
        float2 kh = unpk(sm4[KST0 + jj*PQ + w2]);
        float2 kl = unpk(sm4[KST0 + 4736 + jj*PQ + w2]);
        dot += qh.x*kh.x + qh.x*kl.x + ql.x*kh.x;
        dot += qh.y*kh.y + qh.y*kl.y + ql.y*kh.y;
      }
    }
    dot += __shfl_xor_sync(0xffffffffu, dot, 1);
    dot += __shfl_xor_sync(0xffffffffu, dot, 2);
    if (part == 0) {
      if (!(r & 1)) {
        float mold = mrow[r];
        float mnew = fmaxf(mold, dot);
        float s = __expf(mold - mnew);
        float pd = __expf(dot - mnew);
        sclv[r] = s; pdv[r] = pd;
        lrow[r] = lrow[r] * s + pd;
      } else {
        sclv[r] = 1.f; pdv[r] = 0.f;
      }
    }
  }
  __syncthreads();

  {
    uint32_t* vout = g_v + (size_t)(b * Sn + s0) * 512 + h * 32;
    int r0 = wm + g, r1 = wm + g + 8;
    float s0v = sclv[r0], s1v = sclv[r1];
    float p0v = pdv[r0],  p1v = pdv[r1];
    float il0 = 1.f / lrow[r0], il1 = 1.f / lrow[r1];
    bool ev = !(r0 & 1);
    int j0 = r0 >> 1, j1 = r1 >> 1;
#pragma unroll
    for (int nt = 0; nt < 4; nt++) {
      int p = wn2*16 + nt*4 + q;
      float kv00 = 0.f, kv01 = 0.f, kv10 = 0.f, kv11 = 0.f;
      if (ev) {
        float2 h0 = unpk(sm4[VST0 + j0*PVp + p]);
        float2 l0 = unpk(sm4[VST0 + 1152 + j0*PVp + p]);
        kv00 = h0.x + l0.x; kv01 = h0.y + l0.y;
        float2 h1 = unpk(sm4[VST0 + j1*PVp + p]);
        float2 l1 = unpk(sm4[VST0 + 1152 + j1*PVp + p]);
        kv10 = h1.x + l1.x; kv11 = h1.y + l1.y;
      }
      float f0 = (pacc[nt][0]*s0v + p0v*kv00)*il0;
      float f1 = (pacc[nt][1]*s0v + p0v*kv01)*il0;
      float f2 = (pacc[nt][2]*s1v + p1v*kv10)*il1;
      float f3 = (pacc[nt][3]*s1v + p1v*kv11)*il1;
      size_t i0 = (size_t)r0*512 + p, i1 = (size_t)r1*512 + p;
      vout[i0] = pack_hi(f0, f1); vout[i0 + V_PL] = pack_lo(f0, f1);
      vout[i1] = pack_hi(f2, f3); vout[i1 + V_PL] = pack_lo(f2, f3);
    }
  }
}

extern "C" void kernel_launch(void* const* d_in, const int* in_sizes, int n_in,
                              void* d_out, int out_size) {
  const float* hidden = (const float*)d_in[0];
  const float* wq     = (const float*)d_in[1];
  const float* wkv_a  = (const float*)d_in[2];
  const float* kvg    = (const float*)d_in[3];
  const float* kvb    = (const float*)d_in[4];
  const float* wkvb   = (const float*)d_in[5];
  const float* wo     = (const float*)d_in[6];
  const float* fcw    = (const float*)d_in[7];
  const float* fcb    = (const float*)d_in[8];
  const float* fpw    = (const float*)d_in[9];
  const float* fpb    = (const float*)d_in[10];
  float* out = (float*)d_out;

  uint32_t *pHid, *pWq, *pWkva, *pWo, *pWkvb, *pQ, *pKey, *pQp, *pWkT, *pVh, *pV;
  uint32_t *pCbas, *pPbas, *pFcw, *pFpw;
  float *pKv, *pC2, *pP2;
  cudaGetSymbolAddress((void**)&pHid,  g_hid);
  cudaGetSymbolAddress((void**)&pWq,   g_wq);
  cudaGetSymbolAddress((void**)&pWkva, g_wkva);
  cudaGetSymbolAddress((void**)&pWo,   g_wo);
  cudaGetSymbolAddress((void**)&pWkvb, g_wkvb);
  cudaGetSymbolAddress((void**)&pQ,    g_q);
  cudaGetSymbolAddress((void**)&pKv,   g_kv);
  cudaGetSymbolAddress((void**)&pKey,  g_key);
  cudaGetSymbolAddress((void**)&pQp,   g_qp);
  cudaGetSymbolAddress((void**)&pWkT,  g_wkT);
  cudaGetSymbolAddress((void**)&pVh,   g_vh);
  cudaGetSymbolAddress((void**)&pV,    g_v);
  cudaGetSymbolAddress((void**)&pCbas, g_cbas);
  cudaGetSymbolAddress((void**)&pPbas, g_pbas);
  cudaGetSymbolAddress((void**)&pFcw,  g_fcw);
  cudaGetSymbolAddress((void**)&pFpw,  g_fpw);
  cudaGetSymbolAddress((void**)&pC2,   g_C2);
  cudaGetSymbolAddress((void**)&pP2,   g_P2);

  cudaFuncSetAttribute(tgemmB, cudaFuncAttributeMaxDynamicSharedMemorySize, TGSM_BYTES);
  cudaFuncSetAttribute(attn_mma, cudaFuncAttributeMaxDynamicSharedMemorySize,
                       ATT_SMEM_BYTES);

  /* static streams/events: allocated once per process */
  static cudaStream_t s1 = nullptr, s2 = nullptr;
  static cudaEvent_t e0, eA, eWq, eWkT, eG, eVH, eJ1;
  if (s1 == nullptr) {
    cudaStreamCreateWithFlags(&s1, cudaStreamNonBlocking);
    cudaStreamCreateWithFlags(&s2, cudaStreamNonBlocking);
    cudaEventCreateWithFlags(&e0,   cudaEventDisableTiming);
    cudaEventCreateWithFlags(&eA,   cudaEventDisableTiming);
    cudaEventCreateWithFlags(&eWq,  cudaEventDisableTiming);
    cudaEventCreateWithFlags(&eWkT, cudaEventDisableTiming);
    cudaEventCreateWithFlags(&eG,   cudaEventDisableTiming);
    cudaEventCreateWithFlags(&eVH,  cudaEventDisableTiming);
    cudaEventCreateWithFlags(&eJ1,  cudaEventDisableTiming);
  }

  cudaEventRecord(e0, 0);

  /* s2: wq converter first (overlaps hid conv on main), then wkvb/wkT/wo */
  cudaStreamWaitEvent(s2, e0, 0);
  conv_hl<<<(1536*1024 + 255)/256, 256, 0, s2>>>(wq, pWq, WQ_PL, 1536*1024);
  cudaEventRecord(eWq, s2);
  conv_hl<<<(Hn*128*128 + 255)/256, 256, 0, s2>>>(wkvb, pWkvb, WKVB_PL, Hn*128*128);
  wkT_kernel<<<(Hn*KVRn*32)/256, 256, 0, s2>>>(wkvb);
  cudaEventRecord(eWkT, s2);
  conv_hl<<<(En*512 + 255)/256, 256, 0, s2>>>(wo, pWo, WO_PL, En*512);

  /* s1: gate bases + fc weights + C2/P2 GEMMs, then kv chain */
  cudaStreamWaitEvent(s1, e0, 0);
  gatebasis_kernel<<<Sn, 128, 0, s1>>>();
  conv_hl<<<(64*128 + 255)/256, 256, 0, s1>>>(fcw, pFcw, FW_PL, 64*128);
  conv_hl<<<(64*128 + 255)/256, 256, 0, s1>>>(fpw, pFpw, FW_PL, 64*128);
  tgemmB<<<dim3(1, 16, 1), 256, TGSM_BYTES, s1>>>(pCbas, BAS_PL, 128, 0,
                                   pFcw, FW_PL, 128, 0,
                                   pC2, nullptr, 0, 64, 0, Sn, 64, 256, 1.f);
  tgemmB<<<dim3(1, 16, 1), 256, TGSM_BYTES, s1>>>(pPbas, BAS_PL, 128, 0,
                                   pFpw, FW_PL, 128, 0,
                                   pP2, nullptr, 0, 64, 0, Sn, 64, 256, 1.f);

  /* main: hid + wkva converters */
  conv_hl<<<(BSn*1024 + 255)/256, 256>>>(hidden, pHid, HID_PL, BSn*1024);
  conv_hl<<<(KD*1024 + 255)/256, 256>>>(wkv_a, pWkva, WKVA_PL, KD*1024);
  cudaEventRecord(eA, 0);

  /* s1 continues: kv-proj -> ln -> gate */
  cudaStreamWaitEvent(s1, eA, 0);
  tgemmB<<<dim3(3, 32, 1), 256, TGSM_BYTES, s1>>>(pHid, HID_PL, 1024, 0,
                                   pWkva, WKVA_PL, 1024, 0,
                                   pKv, nullptr, 0, KD, 0, 4096, KD, 2048, 1.f);
  ln_rope_kernel<<<BSn, 256, 0, s1>>>(kvg, kvb);
  gate_kernel<<<BSn, 128, 0, s1>>>(fcb, fpb);
  cudaEventRecord(eG, s1);

  /* s2: vh GEMM after gate */
  cudaStreamWaitEvent(s2, eG, 0);
  tgemmB<<<dim3(1, 32, 16), 256, TGSM_BYTES, s2>>>(pKey, KEY_PL, 144, 0,
                                   pWkvb + 64*128, WKVB_PL, 128, (long long)128*128,
                                   nullptr, pVh, VH_PL, 32, (long long)BSn*32,
                                   4096, Vn, KVRn, 1.f);
  cudaEventRecord(eVH, s2);

  /* main: q-proj (waits wq conv) runs concurrently with s1/s2 */
  cudaStreamWaitEvent(0, eWq, 0);
  tgemmB<<<dim3(12, 32, 1), 256, TGSM_BYTES>>>(pHid, HID_PL, 1024, 0, pWq, WQ_PL, 1024, 0,
                                   nullptr, pQ, Q_PL, 768, 0, 4096, 1536, 2048, 1.f);
  qpack_kernel<<<BSn, 256>>>();
  cudaStreamWaitEvent(0, eWkT, 0);
  tgemmB<<<dim3(2, 32, 16), 256, TGSM_BYTES>>>(pQ, Q_PL, 768, 48,
                                   pWkT, WKT_PL, 32, (long long)KVRn*32,
                                   nullptr, pQp, QP_PL, KD2, (long long)BSn*KD2,
                                   4096, KVRn, NOPEn, SCALEF);
  cudaStreamWaitEvent(0, eVH, 0);
  attn_mma<<<Bn*Hn*32, 256, ATT_SMEM_BYTES>>>();
  tgemmB<<<dim3(16, 32, 1), 256, TGSM_BYTES>>>(pV, V_PL, 512, 0, pWo, WO_PL, 512, 0,
                                   out, nullptr, 0, En, 0, 4096, En, Hn*Vn, 1.f);
  /* join s1/s2 back so capture terminates cleanly */
  cudaEventRecord(eJ1, 0);
  cudaStreamWaitEvent(s1, eJ1, 0);
  cudaStreamWaitEvent(s2, eJ1, 0);
}

// round 17
// speedup vs baseline: 1.1029x; 1.0160x over previous
#include <cuda_runtime.h>
#include <cuda_bf16.h>
#include <math.h>
#include <stdint.h>

#define Bn 2
#define Sn 2048
#define En 2048
#define Hn 16
#define NOPEn 64
#define ROPEn 32
#define Vn 64
#define KVRn 256
#define QKDn 96
#define BSn (Bn*Sn)
#define KD 288
#define KD2 144
#define SCALEF 0.10206207261596577f
#define NEGB (-1e30f)
#define LN1E4_D128 0.07195578415606394f
#define LN1E4_D16  0.5756462732485115f

/* ------------- scratch: PLANAR hl format (hi plane ++ lo plane, u32 bf16-pairs) ------ */
__device__ __align__(16) uint32_t g_hid[(size_t)2 * BSn * 1024];
__device__ __align__(16) uint32_t g_wq[(size_t)2 * 1536 * 1024];
__device__ __align__(16) uint32_t g_wkva[(size_t)2 * KD * 1024];
__device__ __align__(16) uint32_t g_wo[(size_t)2 * En * 512];
__device__ __align__(16) uint32_t g_wkvb[(size_t)2 * Hn * 128 * 128];
__device__ __align__(16) uint32_t g_q[(size_t)2 * BSn * 768];
__device__ __align__(16) float    g_kv[(size_t)BSn * KD];
__device__ __align__(16) uint32_t g_key[(size_t)2 * BSn * KD2];
__device__ __align__(16) uint32_t g_qp[(size_t)2 * Hn * BSn * KD2];
__device__ __align__(16) uint32_t g_wkT[(size_t)2 * Hn * KVRn * 32];
__device__ __align__(16) uint32_t g_vh[(size_t)2 * Hn * BSn * 32];
__device__ __align__(16) uint32_t g_v[(size_t)2 * BSn * 512];
__device__ __align__(16) uint32_t g_cbas[(size_t)2 * Sn * 128];
__device__ __align__(16) uint32_t g_pbas[(size_t)2 * Sn * 128];
__device__ __align__(16) uint32_t g_fcw[(size_t)2 * 64 * 128];
__device__ __align__(16) uint32_t g_fpw[(size_t)2 * 64 * 128];
__device__ __align__(16) float g_C2[Sn * 64];
__device__ __align__(16) float g_P2[Sn * 64];

#define HID_PL  ((long long)BSn*1024)
#define WQ_PL   ((long long)1536*1024)
#define WKVA_PL ((long long)KD*1024)
#define WO_PL   ((long long)En*512)
#define WKVB_PL ((long long)Hn*128*128)
#define Q_PL    ((long long)BSn*768)
#define KEY_PL  ((long long)BSn*KD2)
#define QP_PL   ((long long)Hn*BSn*KD2)
#define WKT_PL  ((long long)Hn*KVRn*32)
#define VH_PL   ((long long)Hn*BSn*32)
#define V_PL    ((long long)BSn*512)
#define BAS_PL  ((long long)Sn*128)
#define FW_PL   ((long long)64*128)

/* ==================== helpers ==================== */
__device__ __forceinline__ void mma16816(float* c, const uint32_t* a, const uint32_t* b) {
  asm volatile(
    "mma.sync.aligned.m16n8k16.row.col.f32.bf16.bf16.f32 "
    "{%0,%1,%2,%3}, {%4,%5,%6,%7}, {%8,%9}, {%0,%1,%2,%3};"
    : "+f"(c[0]), "+f"(c[1]), "+f"(c[2]), "+f"(c[3])
    : "r"(a[0]), "r"(a[1]), "r"(a[2]), "r"(a[3]), "r"(b[0]), "r"(b[1]));
}
#define LDM_X2T(r0_, r1_, addr) \
  asm volatile("ldmatrix.sync.aligned.m8n8.x2.trans.shared.b16 {%0,%1}, [%2];" \
               : "=r"(r0_), "=r"(r1_) : "r"(addr))
#define LDM_X4T(r0_, r1_, r2_, r3_, addr) \
  asm volatile("ldmatrix.sync.aligned.m8n8.x4.trans.shared.b16 {%0,%1,%2,%3}, [%4];" \
               : "=r"(r0_), "=r"(r1_), "=r"(r2_), "=r"(r3_) : "r"(addr))
#define LDM_X4(r0_, r1_, r2_, r3_, addr) \
  asm volatile("ldmatrix.sync.aligned.m8n8.x4.shared.b16 {%0,%1,%2,%3}, [%4];" \
               : "=r"(r0_), "=r"(r1_), "=r"(r2_), "=r"(r3_) : "r"(addr))
#define LDM_X2(r0_, r1_, addr) \
  asm volatile("ldmatrix.sync.aligned.m8n8.x2.shared.b16 {%0,%1}, [%2];" \
               : "=r"(r0_), "=r"(r1_) : "r"(addr))
#define CP_ASYNC16(smaddr, gptr) \
  asm volatile("cp.async.cg.shared.global [%0], [%1], 16;" :: "r"(smaddr), "l"(gptr) : "memory")
#define CP_ASYNC16Z(smaddr, gptr, ssz) \
  asm volatile("cp.async.cg.shared.global [%0], [%1], 16, %2;" :: "r"(smaddr), "l"(gptr), "r"(ssz) : "memory")
#define CP_COMMIT() asm volatile("cp.async.commit_group;" ::: "memory")
#define CP_WAIT0()  asm volatile("cp.async.wait_group 0;" ::: "memory")
#define CP_WAIT1()  asm volatile("cp.async.wait_group 1;" ::: "memory")

__device__ __forceinline__ uint32_t smem_u32(const void* p) {
  uint32_t a;
  asm("{ .reg .u64 t; cvta.to.shared.u64 t, %1; cvt.u32.u64 %0, t; }" : "=r"(a) : "l"(p));
  return a;
}
__device__ __forceinline__ uint32_t pack_hi(float x, float y) {
  __nv_bfloat16 hx = __float2bfloat16_rn(x);
  __nv_bfloat16 hy = __float2bfloat16_rn(y);
  return ((uint32_t)__bfloat16_as_ushort(hy) << 16) | __bfloat16_as_ushort(hx);
}
__device__ __forceinline__ uint32_t pack_lo(float x, float y) {
  __nv_bfloat16 hx = __float2bfloat16_rn(x);
  __nv_bfloat16 hy = __float2bfloat16_rn(y);
  __nv_bfloat16 lx = __float2bfloat16_rn(x - __bfloat162float(hx));
  __nv_bfloat16 ly = __float2bfloat16_rn(y - __bfloat162float(hy));
  return ((uint32_t)__bfloat16_as_ushort(ly) << 16) | __bfloat16_as_ushort(lx);
}
__device__ __forceinline__ float2 unpk(uint32_t u) {
  return make_float2(__bfloat162float(__ushort_as_bfloat16((unsigned short)(u & 0xffff))),
                     __bfloat162float(__ushort_as_bfloat16((unsigned short)(u >> 16))));
}

/* ============ fp32 -> planar hl converter ============ */
__global__ void conv_hl(const float* __restrict__ in, uint32_t* __restrict__ outh,
                        long long plane, int npairs) {
  int i = blockIdx.x * 256 + threadIdx.x;
  if (i < npairs) {
    float2 v = ((const float2*)in)[i];
    outh[i] = pack_hi(v.x, v.y);
    outh[i + plane] = pack_lo(v.x, v.y);
  }
}

/* ============ positional-encoding bases (planar hl) ============ */
__global__ void gatebasis_kernel() {
  int s = blockIdx.x;
  int p = threadIdx.x;
  float dv = expf(-(float)p * LN1E4_D128);
  float aP = (float)s * dv;
  float aC = (float)(s >> 1) * dv;
  float sp = sinf(aP), cp = cosf(aP);
  float sc = sinf(aC), cc = cosf(aC);
  size_t ix = (size_t)s * 128 + p;
  g_pbas[ix] = pack_hi(sp, cp);  g_pbas[ix + BAS_PL] = pack_lo(sp, cp);
  g_cbas[ix] = pack_hi(sc, cc);  g_cbas[ix + BAS_PL] = pack_lo(sc, cc);
}

/* =============== batched tensor GEMM (planar hl): C = alpha*A[M,K]*B[N,K]^T ========== */
#define PITCH 20
#define PLSZ (128*PITCH)
#define STGu (4*PLSZ)
#define TGSM_BYTES (2*STGu*4)

__global__ __launch_bounds__(256, 2) void tgemmB(
    const uint32_t* __restrict__ A, long long aPl, int lda, long long sA,
    const uint32_t* __restrict__ B, long long bPl, int ldb, long long sB,
    float* __restrict__ C, uint32_t* __restrict__ Ch, long long cPl, int ldc, long long sC,
    int M, int N, int K, float alpha)
{
  A += (size_t)blockIdx.z * sA;
  B += (size_t)blockIdx.z * sB;
  if (C)  C  += (size_t)blockIdx.z * sC;
  if (Ch) Ch += (size_t)blockIdx.z * sC;
  extern __shared__ uint32_t dsm[];
  const uint32_t smB = smem_u32(dsm);

  const int tid = threadIdx.x;
  const int wid = tid >> 5, lane = tid & 31;
  const int g = lane >> 2, q = lane & 3;
  const int wm = (wid & 1) * 64;
  const int wn = (wid >> 1) * 32;
  const int bm = blockIdx.y * 128, bn = blockIdx.x * 128;

  const int lt = lane >> 3, lr8 = lane & 7;
  const uint32_t aoffL = (uint32_t)(((wm + (lt & 1) * 8 + lr8) * PITCH + (lt >> 1) * 4) * 4);
  const uint32_t boffL4 = (uint32_t)(((wn + ((lane >> 4) << 3) + lr8) * PITCH + ((lane >> 3) & 1) * 4) * 4);

  const int lrow = tid >> 1, half = tid & 1;
  const uint32_t aZ = (bm + lrow < M) ? 16u : 0u;
  const uint32_t bZ = (bn + lrow < N) ? 16u : 0u;
  int arow = bm + lrow; if (arow >= M) arow = M - 1;
  int brow = bn + lrow; if (brow >= N) brow = N - 1;
  const uint32_t* ArH = A + (size_t)arow * lda + half * 8;
  const uint32_t* BrH = B + (size_t)brow * ldb + half * 8;
  const uint32_t woT = (uint32_t)(lrow * PITCH + half * 8);

  float acc[4][4][4];
#pragma unroll
  for (int i = 0; i < 4; i++)
#pragma unroll
    for (int j = 0; j < 4; j++)
#pragma unroll
      for (int t = 0; t < 4; t++) acc[i][j][t] = 0.f;

#define TG_ISSUE(kk, stg) do {                                             \
    uint32_t wo_ = smB + ((stg)*STGu + woT) * 4;                           \
    const uint32_t* pa_ = ArH + (kk) * 16;                                 \
    CP_ASYNC16Z(wo_,              pa_,       aZ);                          \
    CP_ASYNC16Z(wo_ + 16,         pa_ + 4,   aZ);                          \
    CP_ASYNC16Z(wo_ + PLSZ*4,     pa_ + aPl, aZ);                          \
    CP_ASYNC16Z(wo_ + PLSZ*4+16,  pa_ + aPl + 4, aZ);                      \
    const uint32_t* pb_ = BrH + (kk) * 16;                                 \
    CP_ASYNC16Z(wo_ + 2*PLSZ*4,    pb_,       bZ);                         \
    CP_ASYNC16Z(wo_ + 2*PLSZ*4+16, pb_ + 4,   bZ);                         \
    CP_ASYNC16Z(wo_ + 3*PLSZ*4,    pb_ + bPl, bZ);                         \
    CP_ASYNC16Z(wo_ + 3*PLSZ*4+16, pb_ + bPl + 4, bZ);                     \
  } while (0)

  const int nk = K >> 5;
  TG_ISSUE(0, 0);
  CP_COMMIT();

  for (int k = 0; k < nk; k++) {
    if (k + 1 < nk) {
      TG_ISSUE(k + 1, (k + 1) & 1);
      CP_COMMIT();
      CP_WAIT1();
    } else {
      CP_WAIT0();
    }
    __syncthreads();
    const uint32_t baseS = smB + ((k & 1) * STGu) * 4;
#pragma unroll
    for (int ks = 0; ks < 2; ks++) {
      const uint32_t kcol = baseS + ks * 32;
      uint32_t bh[4][2], bl[4][2];
#pragma unroll
      for (int ntp = 0; ntp < 2; ntp++) {
        uint32_t ba = kcol + 2*PLSZ*4 + boffL4 + ntp * (16*PITCH*4);
        LDM_X4(bh[2*ntp][0], bh[2*ntp][1], bh[2*ntp+1][0], bh[2*ntp+1][1], ba);
        LDM_X4(bl[2*ntp][0], bl[2*ntp][1], bl[2*ntp+1][0], bl[2*ntp+1][1], ba + PLSZ*4);
      }
#pragma unroll
      for (int mt = 0; mt < 4; mt++) {
        uint32_t aa = kcol + aoffL + mt * (16*PITCH*4);
        uint32_t ah[4], al[4];
        LDM_X4(ah[0], ah[1], ah[2], ah[3], aa);
        LDM_X4(al[0], al[1], al[2], al[3], aa + PLSZ*4);
#pragma unroll
        for (int nt = 0; nt < 4; nt++) {
          mma16816(acc[mt][nt], ah, bh[nt]);
          mma16816(acc[mt][nt], ah, bl[nt]);
          mma16816(acc[mt][nt], al, bh[nt]);
        }
      }
    }
    __syncthreads();
  }

#pragma unroll
  for (int mt = 0; mt < 4; mt++) {
    int row = bm + wm + mt * 16 + g;
#pragma unroll
    for (int nt = 0; nt < 4; nt++) {
      int col = bn + wn + nt * 8 + q * 2;
      if (col >= N) continue;
      float a0 = alpha * acc[mt][nt][0], a1 = alpha * acc[mt][nt][1];
      float a2 = alpha * acc[mt][nt][2], a3 = alpha * acc[mt][nt][3];
      if (Ch) {
        if (row < M) {
          size_t ix = (size_t)row * ldc + (col >> 1);
          Ch[ix] = pack_hi(a0, a1); Ch[ix + cPl] = pack_lo(a0, a1);
        }
        if (row + 8 < M) {
          size_t ix = (size_t)(row + 8) * ldc + (col >> 1);
          Ch[ix] = pack_hi(a2, a3); Ch[ix + cPl] = pack_lo(a2, a3);
        }
      } else {
        if (row < M)     *(float2*)(C + (size_t)row * ldc + col)       = make_float2(a0, a1);
        if (row + 8 < M) *(float2*)(C + (size_t)(row + 8) * ldc + col) = make_float2(a2, a3);
      }
    }
  }
}

/* ============ layernorm + rope(k_pe) in place on g_kv ============ */
__global__ void ln_rope_kernel(const float* __restrict__ gam, const float* __restrict__ bet) {
  int row = blockIdx.x;
  float* kv = g_kv + (size_t)row * KD;
  int tid = threadIdx.x;
  float x = kv[tid];
  float s1 = x, s2 = x * x;
#pragma unroll
  for (int o = 16; o; o >>= 1) {
    s1 += __shfl_xor_sync(0xffffffffu, s1, o);
    s2 += __shfl_xor_sync(0xffffffffu, s2, o);
  }
  __shared__ float r1[8], r2[8], mv[2];
  int lane = tid & 31, wid = tid >> 5;
  if (lane == 0) { r1[wid] = s1; r2[wid] = s2; }
  __syncthreads();
  if (tid == 0) {
    float a = 0.f, c = 0.f;
#pragma unroll
    for (int i = 0; i < 8; i++) { a += r1[i]; c += r2[i]; }
    float mean = a * (1.f / 256.f);
    mv[0] = mean;
    mv[1] = rsqrtf(c * (1.f / 256.f) - mean * mean + 1e-5f);
  }
  __syncthreads();
  kv[tid] = (x - mv[0]) * mv[1] * gam[tid] + bet[tid];
  if (tid < 16) {
    int s = row & (Sn - 1);
    float freq = expf(-(float)tid * LN1E4_D16);
    float ang = (float)s * freq;
    float cs = cosf(ang), sn = sinf(ang);
    float x0 = kv[256 + 2*tid], x1 = kv[256 + 2*tid + 1];
    kv[256 + 2*tid]     = x0*cs - x1*sn;
    kv[256 + 2*tid + 1] = x0*sn + x1*cs;
  }
}

/* ============ sparse Wg gating -> planar hl keys (bias added here) ============ */
__global__ void gate_kernel(const float* __restrict__ cb, const float* __restrict__ pb) {
  int row = blockIdx.x;
  int s = row & (Sn - 1);
  int tid = threadIdx.x;
  __shared__ float d1[64], d2[64], w2s[2];
  if (tid < 64) {
    float c2 = g_C2[s*64 + tid] + cb[tid];
    d1[tid] = c2 * (g_P2[s*64 + tid] + pb[tid]);
    d2[tid] = (s & 1) ? c2 * (g_P2[(s-1)*64 + tid] + pb[tid]) : 0.f;
  }
  __syncthreads();
  if (tid == 0) {
    float a = 0.f, b = 0.f;
    for (int i = 0; i < 64; i++) { a += d1[i]; b += d2[i]; }
    w2s[0] = 1.f / (1.f + expf(-a));
    w2s[1] = 1.f / (1.f + expf(-b));
  }
  __syncthreads();
  float wtt = w2s[0], wpre = w2s[1];
  const float* kvr = g_kv + (size_t)row * KD;
  const float* kvp = kvr - KD;
  uint32_t* dsth = g_key + (size_t)row * KD2;
  bool odd = (s & 1);
  for (int c2 = tid; c2 < KD2; c2 += 128) {
    float v0 = wtt * kvr[2*c2],   v1 = wtt * kvr[2*c2+1];
    if (odd) { v0 += wpre * kvp[2*c2]; v1 += wpre * kvp[2*c2+1]; }
    dsth[c2] = pack_hi(v0, v1);
    dsth[c2 + KEY_PL] = pack_lo(v0, v1);
  }
}

/* ============ wkv_b first-64 rows transposed per head (planar) ============ */
__global__ void wkT_kernel(const float* __restrict__ wkvb) {
  int idx = blockIdx.x * 256 + threadIdx.x;
  int d2 = idx & 31;
  int c = (idx >> 5) & 255;
  int h = idx >> 13;
  float v0 = wkvb[((size_t)h * 128 + 2*d2) * 256 + c];
  float v1 = wkvb[((size_t)h * 128 + 2*d2 + 1) * 256 + c];
  size_t ix = ((size_t)h * 256 + c) * 32 + d2;
  g_wkT[ix] = pack_hi(v0, v1);
  g_wkT[ix + WKT_PL] = pack_lo(v0, v1);
}

/* ============ rope + scale q_pe (planar) ============ */
__global__ void qpack_kernel() {
  int row = blockIdx.x;
  int tid = threadIdx.x;
  int h = tid >> 4, i = tid & 15;
  int s = row & (Sn - 1);
  size_t qi = (size_t)row * 768 + h*48 + 32 + i;
  float2 hi = unpk(g_q[qi]), lo = unpk(g_q[qi + Q_PL]);
  float x0 = hi.x + lo.x, x1 = hi.y + lo.y;
  float freq = expf(-(float)i * LN1E4_D16);
  float ang = (float)s * freq;
  float cs = cosf(ang), sn = sinf(ang);
  float y0 = (x0*cs - x1*sn) * SCALEF;
  float y1 = (x0*sn + x1*cs) * SCALEF;
  size_t ox = ((size_t)h * BSn + row) * KD2 + 128 + i;
  g_qp[ox] = pack_hi(y0, y1);
  g_qp[ox + QP_PL] = pack_lo(y0, y1);
}

/* ============ attn: 64-query tiles, V-absorbed flash, x4 ldmatrix fragments ========= */
#define PQ 148
#define PVp 36
#define PP 20
#define QHo 0
#define QLo (64*PQ)
#define KST0 (2*64*PQ)
#define VST0 (KST0 + 2*9472)
#define PFo  (VST0 + 2*2304)
#define PHo  (PFo + 64*33)
#define PLo  (PHo + 64*PP)
#define STo  (PLo + 64*PP)
#define ATT_SMEM_U32 (STo + 256)
#define ATT_SMEM_BYTES (ATT_SMEM_U32 * 4)

__global__ __launch_bounds__(256, 1) void attn_mma() {
  extern __shared__ uint32_t sm4[];
  uint32_t* Qh = sm4 + QHo;
  uint32_t* Ql = sm4 + QLo;
  float*    Pf = (float*)(sm4 + PFo);
  uint32_t* Ph = sm4 + PHo;
  uint32_t* Pl = sm4 + PLo;
  float* mrow = (float*)(sm4 + STo);
  float* lrow = mrow + 64;
  float* sclv = lrow + 64;
  float* pdv  = sclv + 64;

  const int tid = threadIdx.x;
  const int lane = tid & 31, w = tid >> 5;
  const int g = lane >> 2, q = lane & 3;
  const int wm = (w & 3) * 16;
  const int wn2 = w >> 2;

  int idx = blockIdx.x;
  int qt = 31 - (idx & 31);
  int bh = idx >> 5;
  int h = bh & 15, b = bh >> 4;
  int s0 = qt * 64;

  const uint32_t* keyh = g_key + (size_t)b * Sn * KD2;
  const uint32_t* keyl = keyh + KEY_PL;
  const uint32_t* vhh  = g_vh + ((size_t)h * BSn + (size_t)b * Sn) * 32;
  const uint32_t* vhl  = vhh + VH_PL;
  const uint32_t smU = smem_u32(sm4);
  const int jr = tid >> 3, p8 = tid & 7;

  const int lt = lane >> 3, lr8 = lane & 7;
  const uint32_t aoffQ = (uint32_t)(((wm + (lt & 1) * 8 + lr8) * PQ + (lt >> 1) * 4) * 4);
  const uint32_t boffK4 = (uint32_t)(((wn2*16 + ((lane >> 4) << 3) + lr8) * PQ + ((lane >> 3) & 1) * 4) * 4);
  const uint32_t aoffP = (uint32_t)(((wm + (lt & 1) * 8 + lr8) * PP + (lt >> 1) * 4) * 4);
  const uint32_t voffT = (uint32_t)(lane * PVp * 4);

  {
    int r = tid >> 2, p0 = tid & 3;
    const uint32_t* qrh = g_qp + ((size_t)h * BSn + (size_t)b * Sn + s0 + r) * KD2;
    const uint32_t* qrl = qrh + QP_PL;
#pragma unroll 9
    for (int w2 = p0; w2 < 144; w2 += 4) {
      Qh[r*PQ + w2] = qrh[w2];
      Ql[r*PQ + w2] = qrl[w2];
    }
  }
  if (tid < 64) { mrow[tid] = NEGB; lrow[tid] = 0.f; }

  float pacc[4][4];
#pragma unroll
  for (int nt = 0; nt < 4; nt++)
#pragma unroll
    for (int t = 0; t < 4; t++) pacc[nt][t] = 0.f;

#define ISSUE_KV(itn, stg) do {                                                     \
    size_t trow = (size_t)(2*(32*(itn) + jr) + 1);                                  \
    const uint32_t* gkh = keyh + trow * KD2;                                        \
    const uint32_t* gkl = keyl + trow * KD2;                                        \
    uint32_t kb = KST0 + (stg)*9472 + jr*PQ;                                        \
    _Pragma("unroll")                                                               \
    for (int i_ = 0; i_ < 9; i_++) {                                                \
      int c_ = p8 + 8*i_;                                                           \
      int pl_ = (c_ >= 36);                                                         \
      int o_ = pl_ ? c_ - 36 : c_;                                                  \
      const uint32_t* g_ = (pl_ ? gkl : gkh) + o_*4;                                \
      CP_ASYNC16(smU + (kb + pl_*4736 + o_*4)*4, g_);                               \
    }                                                                               \
    const uint32_t* gvh = vhh + trow * 32;                                          \
    const uint32_t* gvl = vhl + trow * 32;                                          \
    uint32_t vb = VST0 + (stg)*2304 + jr*PVp;                                       \
    _Pragma("unroll")                                                               \
    for (int i_ = 0; i_ < 2; i_++) {                                                \
      int c_ = p8 + 8*i_;                                                           \
      int pl_ = (c_ >= 8);                                                          \
      int o_ = c_ & 7;                                                              \
      const uint32_t* g_ = (pl_ ? gvl : gvh) + o_*4;                                \
      CP_ASYNC16(smU + (vb + pl_*1152 + o_*4)*4, g_);                               \
    }                                                                               \
  } while (0)

  ISSUE_KV(0, 0);
  CP_COMMIT();
  CP_WAIT0();
  __syncthreads();

  int st = 0;
  for (int it = 0; it <= qt; it++) {
    bool lastt = (it == qt);
    if (!lastt) { ISSUE_KV(it + 1, st ^ 1); CP_COMMIT(); }

    const uint32_t kbase = smU + (uint32_t)(KST0 + st*9472) * 4;
    float sacc[2][4];
#pragma unroll
    for (int nt = 0; nt < 2; nt++)
#pragma unroll
      for (int t = 0; t < 4; t++) sacc[nt][t] = 0.f;
#pragma unroll
    for (int ks = 0; ks < 18; ks++) {
      uint32_t aa = smU + aoffQ + ks * 32;
      uint32_t ah[4], al[4];
      LDM_X4(ah[0], ah[1], ah[2], ah[3], aa);
      LDM_X4(al[0], al[1], al[2], al[3], aa + QLo*4);
      uint32_t ba = kbase + boffK4 + ks * 32;
      uint32_t bhf[4], blf[4];
      LDM_X4(bhf[0], bhf[1], bhf[2], bhf[3], ba);
      LDM_X4(blf[0], blf[1], blf[2], blf[3], ba + 4736*4);
      mma16816(sacc[0], ah, bhf);
      mma16816(sacc[0], ah, blf);
      mma16816(sacc[0], al, bhf);
      mma16816(sacc[1], ah, bhf + 2);
      mma16816(sacc[1], ah, blf + 2);
      mma16816(sacc[1], al, bhf + 2);
    }
#pragma unroll
    for (int nt = 0; nt < 2; nt++) {
      int c = wn2*16 + nt*8 + 2*q;
      Pf[(wm+g)*33 + c]       = sacc[nt][0];
      Pf[(wm+g)*33 + c + 1]   = sacc[nt][1];
      Pf[(wm+g+8)*33 + c]     = sacc[nt][2];
      Pf[(wm+g+8)*33 + c + 1] = sacc[nt][3];
    }
    __syncthreads();

    {
      int r = tid >> 2, part = tid & 3;
      int jb = part * 8;
      float pv[8];
      float mx = NEGB;
#pragma unroll
      for (int i = 0; i < 8; i++) {
        float sc = Pf[r*33 + jb + i];
        if (lastt && (2*(32*it + jb + i) + 1 > s0 + r)) sc = NEGB;
        pv[i] = sc;
        mx = fmaxf(mx, sc);
      }
      mx = fmaxf(mx, __shfl_xor_sync(0xffffffffu, mx, 1));
      mx = fmaxf(mx, __shfl_xor_sync(0xffffffffu, mx, 2));
      float mold = mrow[r];
      float mnew = fmaxf(mold, mx);
      float su = 0.f;
#pragma unroll
      for (int i = 0; i < 8; i++) {
        float p = __expf(pv[i] - mnew);
        pv[i] = p; su += p;
      }
      su += __shfl_xor_sync(0xffffffffu, su, 1);
      su += __shfl_xor_sync(0xffffffffu, su, 2);
      if (part == 0) {
        float s = __expf(mold - mnew);
        sclv[r] = s;
        lrow[r] = lrow[r] * s + su;
        mrow[r] = mnew;
      }
#pragma unroll
      for (int ii = 0; ii < 4; ii++) {
        Ph[r*PP + part*4 + ii] = pack_hi(pv[2*ii], pv[2*ii+1]);
        Pl[r*PP + part*4 + ii] = pack_lo(pv[2*ii], pv[2*ii+1]);
      }
    }
    __syncthreads();

    {
      float sl = sclv[wm + g], sh2 = sclv[wm + g + 8];
#pragma unroll
      for (int nt = 0; nt < 4; nt++) {
        pacc[nt][0] *= sl;  pacc[nt][1] *= sl;
        pacc[nt][2] *= sh2; pacc[nt][3] *= sh2;
      }
      uint32_t aph[2][4], apl[2][4];
#pragma unroll
      for (int ks = 0; ks < 2; ks++) {
        uint32_t pa = smU + PHo*4 + aoffP + ks * 32;
        LDM_X4(aph[ks][0], aph[ks][1], aph[ks][2], aph[ks][3], pa);
        LDM_X4(apl[ks][0], apl[ks][1], apl[ks][2], apl[ks][3], pa + (PLo - PHo)*4);
      }
      uint32_t vB = smU + (uint32_t)(VST0 + st*2304) * 4 + voffT;
#pragma unroll
      for (int nt = 0; nt < 4; nt++) {
        uint32_t co = (uint32_t)(wn2*16 + nt*4) * 4;
        uint32_t bh0[2], bl0[2], bh1[2], bl1[2];
        LDM_X4T(bh0[0], bh0[1], bh1[0], bh1[1], vB + co);
        LDM_X4T(bl0[0], bl0[1], bl1[0], bl1[1], vB + co + 1152u*4);
        mma16816(pacc[nt], aph[0], bh0);
        mma16816(pacc[nt], aph[0], bl0);
        mma16816(pacc[nt], apl[0], bh0);
        mma16816(pacc[nt], aph[1], bh1);
        mma16816(pacc[nt], aph[1], bl1);
        mma16816(pacc[nt], apl[1], bh1);
      }
    }
    CP_WAIT0();
    __syncthreads();
    st ^= 1;
  }

  {
    size_t trow = (size_t)(s0 + 2*jr);
    const uint32_t* krh = keyh + trow * KD2;
    const uint32_t* krl = keyl + trow * KD2;
#pragma unroll 18
    for (int i = 0; i < 18; i++) {
      sm4[KST0 + jr*PQ + p8 + 8*i] = krh[p8 + 8*i];
      sm4[KST0 + 4736 + jr*PQ + p8 + 8*i] = krl[p8 + 8*i];
    }
    const uint32_t* gvh = vhh + trow * 32;
    const uint32_t* gvl = vhl + trow * 32;
#pragma unroll 4
    for (int i = 0; i < 4; i++) {
      sm4[VST0 + jr*PVp + (p8<<2) + i] = gvh[(p8<<2) + i];
      sm4[VST0 + 1152 + jr*PVp + (p8<<2) + i] = gvl[(p8<<2) + i];
    }
  }
  __syncthreads();
  {
    int r = tid >> 2, part = tid & 3;
    float dot = 0.f;
    if (!(r & 1)) {
      int jj = r >> 1;
      for (int w2 = part*36; w2 < part*36 + 36; w2++) {
        float2 qh = unpk(Qh[r*PQ + w2]);
        float2 ql = unpk(Ql[r*PQ + w2]);
        float2 kh = unpk(sm4[KST0 + jj*PQ + w2]);
        float2 kl = unpk(sm4[KST0 + 4736 + jj*PQ + w2]);
        dot += qh.x*kh.x + qh.x*kl.x + ql.x*kh.x;
        dot += qh.y*kh.y + qh.y*kl.y + ql.y*kh.y;
      }
    }
    dot += __shfl_xor_sync(0xffffffffu, dot, 1);
    dot += __shfl_xor_sync(0xffffffffu, dot, 2);
    if (part == 0) {
      if (!(r & 1)) {
        float mold = mrow[r];
        float mnew = fmaxf(mold, dot);
        float s = __expf(mold - mnew);
        float pd = __expf(dot - mnew);
        sclv[r] = s; pdv[r] = pd;
        lrow[r] = lrow[r] * s + pd;
      } else {
        sclv[r] = 1.f; pdv[r] = 0.f;
      }
    }
  }
  __syncthreads();

  {
    uint32_t* vout = g_v + (size_t)(b * Sn + s0) * 512 + h * 32;
    int r0 = wm + g, r1 = wm + g + 8;
    float s0v = sclv[r0], s1v = sclv[r1];
    float p0v = pdv[r0],  p1v = pdv[r1];
    float il0 = 1.f / lrow[r0], il1 = 1.f / lrow[r1];
    bool ev = !(r0 & 1);
    int j0 = r0 >> 1, j1 = r1 >> 1;
#pragma unroll
    for (int nt = 0; nt < 4; nt++) {
      int p = wn2*16 + nt*4 + q;
      float kv00 = 0.f, kv01 = 0.f, kv10 = 0.f, kv11 = 0.f;
      if (ev) {
        float2 h0 = unpk(sm4[VST0 + j0*PVp + p]);
        float2 l0 = unpk(sm4[VST0 + 1152 + j0*PVp + p]);
        kv00 = h0.x + l0.x; kv01 = h0.y + l0.y;
        float2 h1 = unpk(sm4[VST0 + j1*PVp + p]);
        float2 l1 = unpk(sm4[VST0 + 1152 + j1*PVp + p]);
        kv10 = h1.x + l1.x; kv11 = h1.y + l1.y;
      }
      float f0 = (pacc[nt][0]*s0v + p0v*kv00)*il0;
      float f1 = (pacc[nt][1]*s0v + p0v*kv01)*il0;
      float f2 = (pacc[nt][2]*s1v + p1v*kv10)*il1;
      float f3 = (pacc[nt][3]*s1v + p1v*kv11)*il1;
      size_t i0 = (size_t)r0*512 + p, i1 = (size_t)r1*512 + p;
      vout[i0] = pack_hi(f0, f1); vout[i0 + V_PL] = pack_lo(f0, f1);
      vout[i1] = pack_hi(f2, f3); vout[i1 + V_PL] = pack_lo(f2, f3);
    }
  }
}

extern "C" void kernel_launch(void* const* d_in, const int* in_sizes, int n_in,
                              void* d_out, int out_size) {
  const float* hidden = (const float*)d_in[0];
  const float* wq     = (const float*)d_in[1];
  const float* wkv_a  = (const float*)d_in[2];
  const float* kvg    = (const float*)d_in[3];
  const float* kvb    = (const float*)d_in[4];
  const float* wkvb   = (const float*)d_in[5];
  const float* wo     = (const float*)d_in[6];
  const float* fcw    = (const float*)d_in[7];
  const float* fcb    = (const float*)d_in[8];
  const float* fpw    = (const float*)d_in[9];
  const float* fpb    = (const float*)d_in[10];
  float* out = (float*)d_out;

  uint32_t *pHid, *pWq, *pWkva, *pWo, *pWkvb, *pQ, *pKey, *pQp, *pWkT, *pVh, *pV;
  uint32_t *pCbas, *pPbas, *pFcw, *pFpw;
  float *pKv, *pC2, *pP2;
  cudaGetSymbolAddress((void**)&pHid,  g_hid);
  cudaGetSymbolAddress((void**)&pWq,   g_wq);
  cudaGetSymbolAddress((void**)&pWkva, g_wkva);
  cudaGetSymbolAddress((void**)&pWo,   g_wo);
  cudaGetSymbolAddress((void**)&pWkvb, g_wkvb);
  cudaGetSymbolAddress((void**)&pQ,    g_q);
  cudaGetSymbolAddress((void**)&pKv,   g_kv);
  cudaGetSymbolAddress((void**)&pKey,  g_key);
  cudaGetSymbolAddress((void**)&pQp,   g_qp);
  cudaGetSymbolAddress((void**)&pWkT,  g_wkT);
  cudaGetSymbolAddress((void**)&pVh,   g_vh);
  cudaGetSymbolAddress((void**)&pV,    g_v);
  cudaGetSymbolAddress((void**)&pCbas, g_cbas);
  cudaGetSymbolAddress((void**)&pPbas, g_pbas);
  cudaGetSymbolAddress((void**)&pFcw,  g_fcw);
  cudaGetSymbolAddress((void**)&pFpw,  g_fpw);
  cudaGetSymbolAddress((void**)&pC2,   g_C2);
  cudaGetSymbolAddress((void**)&pP2,   g_P2);

  cudaFuncSetAttribute(tgemmB, cudaFuncAttributeMaxDynamicSharedMemorySize, TGSM_BYTES);
  cudaFuncSetAttribute(attn_mma, cudaFuncAttributeMaxDynamicSharedMemorySize,
                       ATT_SMEM_BYTES);

  /* static streams/events: allocated once per process */
  static cudaStream_t s1 = nullptr, s2 = nullptr;
  static cudaEvent_t e0, eA, eWq, eWkT, eG, eVH, eJ1;
  if (s1 == nullptr) {
    cudaStreamCreateWithFlags(&s1, cudaStreamNonBlocking);
    cudaStreamCreateWithFlags(&s2, cudaStreamNonBlocking);
    cudaEventCreateWithFlags(&e0,   cudaEventDisableTiming);
    cudaEventCreateWithFlags(&eA,   cudaEventDisableTiming);
    cudaEventCreateWithFlags(&eWq,  cudaEventDisableTiming);
    cudaEventCreateWithFlags(&eWkT, cudaEventDisableTiming);
    cudaEventCreateWithFlags(&eG,   cudaEventDisableTiming);
    cudaEventCreateWithFlags(&eVH,  cudaEventDisableTiming);
    cudaEventCreateWithFlags(&eJ1,  cudaEventDisableTiming);
  }

  cudaEventRecord(e0, 0);

  /* s2: wq converter first (overlaps hid conv on main), then wkvb/wkT/wo */
  cudaStreamWaitEvent(s2, e0, 0);
  conv_hl<<<(1536*1024 + 255)/256, 256, 0, s2>>>(wq, pWq, WQ_PL, 1536*1024);
  cudaEventRecord(eWq, s2);
  conv_hl<<<(Hn*128*128 + 255)/256, 256, 0, s2>>>(wkvb, pWkvb, WKVB_PL, Hn*128*128);
  wkT_kernel<<<(Hn*KVRn*32)/256, 256, 0, s2>>>(wkvb);
  cudaEventRecord(eWkT, s2);
  conv_hl<<<(En*512 + 255)/256, 256, 0, s2>>>(wo, pWo, WO_PL, En*512);

  /* s1: gate bases + fc weights + C2/P2 GEMMs, then kv chain */
  cudaStreamWaitEvent(s1, e0, 0);
  gatebasis_kernel<<<Sn, 128, 0, s1>>>();
  conv_hl<<<(64*128 + 255)/256, 256, 0, s1>>>(fcw, pFcw, FW_PL, 64*128);
  conv_hl<<<(64*128 + 255)/256, 256, 0, s1>>>(fpw, pFpw, FW_PL, 64*128);
  tgemmB<<<dim3(1, 16, 1), 256, TGSM_BYTES, s1>>>(pCbas, BAS_PL, 128, 0,
                                   pFcw, FW_PL, 128, 0,
                                   pC2, nullptr, 0, 64, 0, Sn, 64, 256, 1.f);
  tgemmB<<<dim3(1, 16, 1), 256, TGSM_BYTES, s1>>>(pPbas, BAS_PL, 128, 0,
                                   pFpw, FW_PL, 128, 0,
                                   pP2, nullptr, 0, 64, 0, Sn, 64, 256, 1.f);

  /* main: hid + wkva converters */
  conv_hl<<<(BSn*1024 + 255)/256, 256>>>(hidden, pHid, HID_PL, BSn*1024);
  conv_hl<<<(KD*1024 + 255)/256, 256>>>(wkv_a, pWkva, WKVA_PL, KD*1024);
  cudaEventRecord(eA, 0);

  /* s1 continues: kv-proj -> ln -> gate */
  cudaStreamWaitEvent(s1, eA, 0);
  tgemmB<<<dim3(3, 32, 1), 256, TGSM_BYTES, s1>>>(pHid, HID_PL, 1024, 0,
                                   pWkva, WKVA_PL, 1024, 0,
                                   pKv, nullptr, 0, KD, 0, 4096, KD, 2048, 1.f);
  ln_rope_kernel<<<BSn, 256, 0, s1>>>(kvg, kvb);
  gate_kernel<<<BSn, 128, 0, s1>>>(fcb, fpb);
  cudaEventRecord(eG, s1);

  /* s2: vh GEMM after gate */
  cudaStreamWaitEvent(s2, eG, 0);
  tgemmB<<<dim3(1, 32, 16), 256, TGSM_BYTES, s2>>>(pKey, KEY_PL, 144, 0,
                                   pWkvb + 64*128, WKVB_PL, 128, (long long)128*128,
                                   nullptr, pVh, VH_PL, 32, (long long)BSn*32,
                                   4096, Vn, KVRn, 1.f);
  cudaEventRecord(eVH, s2);

  /* main: q-proj (waits wq conv) runs concurrently with s1/s2 */
  cudaStreamWaitEvent(0, eWq, 0);
  tgemmB<<<dim3(12, 32, 1), 256, TGSM_BYTES>>>(pHid, HID_PL, 1024, 0, pWq, WQ_PL, 1024, 0,
                                   nullptr, pQ, Q_PL, 768, 0, 4096, 1536, 2048, 1.f);
  qpack_kernel<<<BSn, 256>>>();
  cudaStreamWaitEvent(0, eWkT, 0);
  tgemmB<<<dim3(2, 32, 16), 256, TGSM_BYTES>>>(pQ, Q_PL, 768, 48,
                                   pWkT, WKT_PL, 32, (long long)KVRn*32,
                                   nullptr, pQp, QP_PL, KD2, (long long)BSn*KD2,
                                   4096, KVRn, NOPEn, SCALEF);
  cudaStreamWaitEvent(0, eVH, 0);
  attn_mma<<<Bn*Hn*32, 256, ATT_SMEM_BYTES>>>();
  tgemmB<<<dim3(16, 32, 1), 256, TGSM_BYTES>>>(pV, V_PL, 512, 0, pWo, WO_PL, 512, 0,
                                   out, nullptr, 0, En, 0, 4096, En, Hn*Vn, 1.f);
  /* join s1/s2 back so capture terminates cleanly */
  cudaEventRecord(eJ1, 0);
  cudaStreamWaitEvent(s1, eJ1, 0);
  cudaStreamWaitEvent(s2, eJ1, 0);
}